// round 1
// baseline (speedup 1.0000x reference)
#include <cuda_runtime.h>
#include <math.h>

#define B_ 2
#define S_ 2048
#define D_ 1024
#define H_ 16
#define DK_ 64
#define M_ (B_*S_)

// Scratch (allocation-free rule: __device__ globals)
__device__ float g_Qp[(size_t)B_*S_*D_];
__device__ float g_Kp[(size_t)B_*S_*D_];
__device__ float g_Vp[(size_t)B_*S_*D_];
__device__ float g_Att[(size_t)B_*S_*D_];

// ---------------------------------------------------------------------------
// GEMM: C[M,N] = A[M,K] @ W[N,K]^T + bias[N]   (M=4096, N=1024, K=1024 fixed)
// 128x128 tile, BK=16, 256 threads, 8x8 per thread.
// ---------------------------------------------------------------------------
__device__ __forceinline__ void gemm_body(const float* __restrict__ A,
                                          const float* __restrict__ W,
                                          const float* __restrict__ bias,
                                          float* __restrict__ C)
{
    __shared__ float As[16][132];   // padded: conflict-free transposed stores
    __shared__ float Bs[16][132];

    const int tid = threadIdx.x;
    const int tx = tid & 15, ty = tid >> 4;
    const int m0 = blockIdx.y * 128, n0 = blockIdx.x * 128;

    float acc[8][8];
    #pragma unroll
    for (int i = 0; i < 8; i++)
        #pragma unroll
        for (int j = 0; j < 8; j++) acc[i][j] = 0.f;

    for (int k0 = 0; k0 < 1024; k0 += 16) {
        #pragma unroll
        for (int t = 0; t < 2; t++) {
            int s4 = tid + t * 256;          // 512 float4 slots per operand
            int r  = s4 >> 2;                // 0..127 row in tile
            int qd = s4 & 3;                 // 0..3 k-quad
            float4 va = *(const float4*)(A + (size_t)(m0 + r) * 1024 + k0 + qd * 4);
            As[qd*4+0][r] = va.x; As[qd*4+1][r] = va.y;
            As[qd*4+2][r] = va.z; As[qd*4+3][r] = va.w;
            float4 vb = *(const float4*)(W + (size_t)(n0 + r) * 1024 + k0 + qd * 4);
            Bs[qd*4+0][r] = vb.x; Bs[qd*4+1][r] = vb.y;
            Bs[qd*4+2][r] = vb.z; Bs[qd*4+3][r] = vb.w;
        }
        __syncthreads();

        #pragma unroll
        for (int kk = 0; kk < 16; kk++) {
            float4 a0 = *(const float4*)&As[kk][ty*8];
            float4 a1 = *(const float4*)&As[kk][ty*8+4];
            float4 b0 = *(const float4*)&Bs[kk][tx*8];
            float4 b1 = *(const float4*)&Bs[kk][tx*8+4];
            float a[8] = {a0.x,a0.y,a0.z,a0.w,a1.x,a1.y,a1.z,a1.w};
            float b[8] = {b0.x,b0.y,b0.z,b0.w,b1.x,b1.y,b1.z,b1.w};
            #pragma unroll
            for (int i = 0; i < 8; i++)
                #pragma unroll
                for (int j = 0; j < 8; j++)
                    acc[i][j] = fmaf(a[i], b[j], acc[i][j]);
        }
        __syncthreads();
    }

    #pragma unroll
    for (int i = 0; i < 8; i++) {
        size_t row = (size_t)(m0 + ty*8 + i);
        #pragma unroll
        for (int j0 = 0; j0 < 8; j0 += 4) {
            int col = n0 + tx*8 + j0;
            float4 o;
            o.x = acc[i][j0+0] + bias[col+0];
            o.y = acc[i][j0+1] + bias[col+1];
            o.z = acc[i][j0+2] + bias[col+2];
            o.w = acc[i][j0+3] + bias[col+3];
            *(float4*)(C + row * 1024 + col) = o;
        }
    }
}

__global__ __launch_bounds__(256)
void qkv_gemm_kernel(const float* __restrict__ q, const float* __restrict__ k,
                     const float* __restrict__ v,
                     const float* __restrict__ Wq, const float* __restrict__ bq,
                     const float* __restrict__ Wk, const float* __restrict__ bk,
                     const float* __restrict__ Wv, const float* __restrict__ bv)
{
    const float* A; const float* W; const float* bias; float* C;
    if (blockIdx.z == 0)      { A = q; W = Wq; bias = bq; C = g_Qp; }
    else if (blockIdx.z == 1) { A = k; W = Wk; bias = bk; C = g_Kp; }
    else                      { A = v; W = Wv; bias = bv; C = g_Vp; }
    gemm_body(A, W, bias, C);
}

__global__ __launch_bounds__(256)
void out_gemm_kernel(const float* __restrict__ Wo, const float* __restrict__ bo,
                     float* __restrict__ out)
{
    gemm_body(g_Att, Wo, bo, out);
}

// ---------------------------------------------------------------------------
// RoPE in-place on g_Qp / g_Kp. One thread per (b,s,h,j<32) pair.
// ---------------------------------------------------------------------------
__global__ void rope_kernel()
{
    __shared__ float invf[32];
    if (threadIdx.x < 32)
        invf[threadIdx.x] = (float)exp(-(double)threadIdx.x * 0.28782313662425574); // ln(10000)/32
    __syncthreads();

    int idx = blockIdx.x * blockDim.x + threadIdx.x;
    float* buf = (blockIdx.y == 0) ? g_Qp : g_Kp;
    int j = idx & 31;
    int h = (idx >> 5) & (H_ - 1);
    int s = (idx >> 9) & (S_ - 1);
    int b = idx >> 20;

    float ang = (float)s * invf[j];
    float sn, c;
    sincosf(ang, &sn, &c);

    size_t base = ((size_t)(b * S_ + s)) * D_ + h * DK_ + j;
    float x1 = buf[base], x2 = buf[base + 32];
    buf[base]      = x1 * c - x2 * sn;
    buf[base + 32] = x1 * sn + x2 * c;
}

// ---------------------------------------------------------------------------
// Causal flash attention: 64x64 tiles, 256 threads, 4x4 per thread.
// Layouts: Qs[d][i], Ks[d][j], Vs[j][dv], Ps[j][i]  (all rows padded to 68)
// ---------------------------------------------------------------------------
__global__ __launch_bounds__(256) void attn_kernel()
{
    extern __shared__ float sm[];
    float (*Qs)[68] = reinterpret_cast<float(*)[68]>(sm);
    float (*Ks)[68] = reinterpret_cast<float(*)[68]>(sm + 64*68);
    float (*Vs)[68] = reinterpret_cast<float(*)[68]>(sm + 2*64*68);
    float (*Ps)[68] = reinterpret_cast<float(*)[68]>(sm + 3*64*68);

    const int tid = threadIdx.x;
    const int tx = tid & 15, ty = tid >> 4;
    const int qt = (int)(gridDim.x - 1) - (int)blockIdx.x;  // heavy blocks first
    const int h = blockIdx.y, b = blockIdx.z;

    const float* Qb = g_Qp + ((size_t)b * S_ + qt * 64) * D_ + h * DK_;
    const float* Kb = g_Kp + (size_t)b * S_ * D_ + h * DK_;
    const float* Vb = g_Vp + (size_t)b * S_ * D_ + h * DK_;

    // Load Q tile transposed: Qs[d][i]
    #pragma unroll
    for (int t = 0; t < 4; t++) {
        int s4 = tid + t * 256;        // 1024 float4 slots
        int r  = s4 >> 4;              // 0..63
        int qd = s4 & 15;              // 0..15
        float4 v = *(const float4*)(Qb + (size_t)r * D_ + qd * 4);
        Qs[qd*4+0][r] = v.x; Qs[qd*4+1][r] = v.y;
        Qs[qd*4+2][r] = v.z; Qs[qd*4+3][r] = v.w;
    }

    float m[4], l[4], o[4][4];
    #pragma unroll
    for (int i = 0; i < 4; i++) {
        m[i] = -INFINITY; l[i] = 0.f;
        #pragma unroll
        for (int j = 0; j < 4; j++) o[i][j] = 0.f;
    }

    for (int kt = 0; kt <= qt; kt++) {
        __syncthreads();   // prior PV reads of Ks/Vs/Ps complete
        #pragma unroll
        for (int t = 0; t < 4; t++) {
            int s4 = tid + t * 256;
            int r  = s4 >> 4, qd = s4 & 15;
            const float* Kr = Kb + ((size_t)(kt * 64 + r)) * D_;
            float4 kv = *(const float4*)(Kr + qd * 4);
            Ks[qd*4+0][r] = kv.x; Ks[qd*4+1][r] = kv.y;
            Ks[qd*4+2][r] = kv.z; Ks[qd*4+3][r] = kv.w;
            const float* Vr = Vb + ((size_t)(kt * 64 + r)) * D_;
            *(float4*)&Vs[r][qd*4] = *(const float4*)(Vr + qd * 4);
        }
        __syncthreads();

        // S = Q @ K^T  (outer product over d)
        float sv[4][4];
        #pragma unroll
        for (int i = 0; i < 4; i++)
            #pragma unroll
            for (int j = 0; j < 4; j++) sv[i][j] = 0.f;

        #pragma unroll 16
        for (int d = 0; d < 64; d++) {
            float4 qv = *(const float4*)&Qs[d][ty*4];
            float4 kv = *(const float4*)&Ks[d][tx*4];
            float aa[4] = {qv.x, qv.y, qv.z, qv.w};
            float bb[4] = {kv.x, kv.y, kv.z, kv.w};
            #pragma unroll
            for (int ii = 0; ii < 4; ii++)
                #pragma unroll
                for (int jj = 0; jj < 4; jj++)
                    sv[ii][jj] = fmaf(aa[ii], bb[jj], sv[ii][jj]);
        }

        const float scale = 0.125f;   // 1/sqrt(64)
        const bool diag = (kt == qt);

        #pragma unroll
        for (int ii = 0; ii < 4; ii++) {
            int qi = qt * 64 + ty * 4 + ii;
            float rm = -INFINITY;
            #pragma unroll
            for (int jj = 0; jj < 4; jj++) {
                float x = sv[ii][jj] * scale;
                if (diag && (kt * 64 + tx * 4 + jj) > qi) x = -INFINITY;
                sv[ii][jj] = x;
                rm = fmaxf(rm, x);
            }
            #pragma unroll
            for (int off = 1; off < 16; off <<= 1)
                rm = fmaxf(rm, __shfl_xor_sync(0xffffffffu, rm, off));
            float mn = fmaxf(m[ii], rm);
            float alpha = __expf(m[ii] - mn);
            float rs = 0.f;
            #pragma unroll
            for (int jj = 0; jj < 4; jj++) {
                float p = __expf(sv[ii][jj] - mn);
                sv[ii][jj] = p; rs += p;
            }
            #pragma unroll
            for (int off = 1; off < 16; off <<= 1)
                rs += __shfl_xor_sync(0xffffffffu, rs, off);
            l[ii] = l[ii] * alpha + rs;
            m[ii] = mn;
            #pragma unroll
            for (int jj = 0; jj < 4; jj++) o[ii][jj] *= alpha;
        }

        // Write P transposed: Ps[j][i]
        #pragma unroll
        for (int ii = 0; ii < 4; ii++)
            #pragma unroll
            for (int jj = 0; jj < 4; jj++)
                Ps[tx*4+jj][ty*4+ii] = sv[ii][jj];
        __syncthreads();

        // O += P @ V (outer product over j)
        #pragma unroll 16
        for (int j = 0; j < 64; j++) {
            float4 pv = *(const float4*)&Ps[j][ty*4];
            float4 vv = *(const float4*)&Vs[j][tx*4];
            float pa[4] = {pv.x, pv.y, pv.z, pv.w};
            float vb4[4] = {vv.x, vv.y, vv.z, vv.w};
            #pragma unroll
            for (int ii = 0; ii < 4; ii++)
                #pragma unroll
                for (int jj = 0; jj < 4; jj++)
                    o[ii][jj] = fmaf(pa[ii], vb4[jj], o[ii][jj]);
        }
    }

    float* Ob = g_Att + ((size_t)b * S_ + qt * 64) * D_ + h * DK_;
    #pragma unroll
    for (int ii = 0; ii < 4; ii++) {
        float inv = 1.0f / l[ii];
        float4 ov = { o[ii][0]*inv, o[ii][1]*inv, o[ii][2]*inv, o[ii][3]*inv };
        *(float4*)(Ob + (size_t)(ty*4+ii) * D_ + tx*4) = ov;
    }
}

// ---------------------------------------------------------------------------
extern "C" void kernel_launch(void* const* d_in, const int* in_sizes, int n_in,
                              void* d_out, int out_size)
{
    (void)in_sizes; (void)n_in; (void)out_size;
    const float* q  = (const float*)d_in[0];
    const float* k  = (const float*)d_in[1];
    const float* v  = (const float*)d_in[2];
    // d_in[3] = mask (causal, implicit in kernel)
    const float* Wq = (const float*)d_in[4];
    const float* bq = (const float*)d_in[5];
    const float* Wk = (const float*)d_in[6];
    const float* bk = (const float*)d_in[7];
    const float* Wv = (const float*)d_in[8];
    const float* bv = (const float*)d_in[9];
    const float* Wo = (const float*)d_in[10];
    const float* bo = (const float*)d_in[11];
    float* out = (float*)d_out;

    const int attn_smem = 4 * 64 * 68 * 4;  // 69632 B
    cudaFuncSetAttribute(attn_kernel, cudaFuncAttributeMaxDynamicSharedMemorySize, attn_smem);

    dim3 gqkv(1024/128, M_/128, 3);
    qkv_gemm_kernel<<<gqkv, 256>>>(q, k, v, Wq, bq, Wk, bk, Wv, bv);

    rope_kernel<<<dim3((B_*S_*H_*32)/256, 2), 256>>>();

    attn_kernel<<<dim3(S_/64, H_, B_), 256, attn_smem>>>();

    out_gemm_kernel<<<dim3(1024/128, M_/128), 256>>>(Wo, bo, out);
}

// round 3
// speedup vs baseline: 1.4210x; 1.4210x over previous
#include <cuda_runtime.h>
#include <math.h>
#include <stdint.h>

#define B_ 2
#define S_ 2048
#define D_ 1024
#define H_ 16
#define M_ (B_*S_)

// Scratch (allocation-free rule: __device__ globals)
__device__ float g_Qp[(size_t)B_*S_*D_];
__device__ float g_Kp[(size_t)B_*S_*D_];
__device__ float g_Vp[(size_t)B_*S_*D_];
__device__ float g_Att[(size_t)B_*S_*D_];

__device__ __forceinline__ uint32_t f2tf32(float x) {
    uint32_t r;
    asm("cvt.rna.tf32.f32 %0, %1;" : "=r"(r) : "f"(x));
    return r;
}

__device__ __forceinline__ void mma_tf32(float* d, const uint32_t* a, const uint32_t* b) {
    asm volatile(
        "mma.sync.aligned.m16n8k8.row.col.f32.tf32.tf32.f32 "
        "{%0,%1,%2,%3}, {%4,%5,%6,%7}, {%8,%9}, {%0,%1,%2,%3};"
        : "+f"(d[0]), "+f"(d[1]), "+f"(d[2]), "+f"(d[3])
        : "r"(a[0]), "r"(a[1]), "r"(a[2]), "r"(a[3]), "r"(b[0]), "r"(b[1]));
}

// ---------------------------------------------------------------------------
// tf32 mma.sync GEMM: C[M,N] = A[M,K] @ W[N,K]^T + bias   (K=1024, N=1024)
// CTA 128x128, BK=32, 256 threads (8 warps, 2x4), warp tile 64x32.
// Warp's 4 n-tiles are scattered {+0,+32,+64,+96} so RoPE pairs (j, j+32)
// stay within one thread's accumulators.
// smem: [k][m] transposed, stride 132 words (<=2-way conflicts).
// ---------------------------------------------------------------------------
#define STRIDE_ 132
#define STAGE_WORDS_ (32*STRIDE_)

template<int DO_ROPE>
__device__ __forceinline__ void gemm_mma_body(const float* __restrict__ A,
                                              const float* __restrict__ W,
                                              const float* __restrict__ bias,
                                              float* __restrict__ C)
{
    extern __shared__ uint32_t sm_[];
    uint32_t* As = sm_;                       // [2][32][132]
    uint32_t* Bs = sm_ + 2 * STAGE_WORDS_;    // [2][32][132]

    const int tid  = threadIdx.x;
    const int lane = tid & 31, w = tid >> 5;
    const int warpM = w & 1, warpN = w >> 1;         // 2 x 4
    const int g = lane >> 2, tg = lane & 3;
    const int m0 = blockIdx.y * 128, n0 = blockIdx.x * 128;

    // loader mapping (bijective, 2-way STS conflicts, 64B gmem segments)
    const int rbase = 8 * (w & 3) + g;               // + 32*t
    const int q     = (lane & 3) + 4 * (w >> 2);     // 0..7 (16B quad in k)

    float4 ra[4], rb[4];
    #define LOAD_TILE(k0_)                                                     \
        _Pragma("unroll")                                                      \
        for (int t = 0; t < 4; t++) {                                          \
            int r = rbase + 32 * t;                                            \
            ra[t] = *(const float4*)(A + (size_t)(m0 + r) * 1024 + (k0_) + q * 4); \
            rb[t] = *(const float4*)(W + (size_t)(n0 + r) * 1024 + (k0_) + q * 4); \
        }
    #define STORE_TILE(buf_)                                                   \
        _Pragma("unroll")                                                      \
        for (int t = 0; t < 4; t++) {                                          \
            int r = rbase + 32 * t;                                            \
            uint32_t* Ad = As + (buf_) * STAGE_WORDS_ + r;                     \
            uint32_t* Bd = Bs + (buf_) * STAGE_WORDS_ + r;                     \
            Ad[(4*q+0)*STRIDE_] = f2tf32(ra[t].x);                             \
            Ad[(4*q+1)*STRIDE_] = f2tf32(ra[t].y);                             \
            Ad[(4*q+2)*STRIDE_] = f2tf32(ra[t].z);                             \
            Ad[(4*q+3)*STRIDE_] = f2tf32(ra[t].w);                             \
            Bd[(4*q+0)*STRIDE_] = f2tf32(rb[t].x);                             \
            Bd[(4*q+1)*STRIDE_] = f2tf32(rb[t].y);                             \
            Bd[(4*q+2)*STRIDE_] = f2tf32(rb[t].z);                             \
            Bd[(4*q+3)*STRIDE_] = f2tf32(rb[t].w);                             \
        }

    float acc[4][4][4];
    #pragma unroll
    for (int i = 0; i < 4; i++)
        #pragma unroll
        for (int j = 0; j < 4; j++)
            #pragma unroll
            for (int x = 0; x < 4; x++) acc[i][j][x] = 0.f;

    LOAD_TILE(0);
    STORE_TILE(0);
    __syncthreads();

    #pragma unroll 1
    for (int s = 0; s < 32; s++) {
        if (s < 31) { LOAD_TILE((s + 1) * 32); }

        const uint32_t* Ab = As + (s & 1) * STAGE_WORDS_;
        const uint32_t* Bb = Bs + (s & 1) * STAGE_WORDS_;
        #pragma unroll
        for (int ks = 0; ks < 4; ks++) {
            const int krow = ks * 8 + tg;
            uint32_t af[4][4];
            #pragma unroll
            for (int mt = 0; mt < 4; mt++) {
                int base = krow * STRIDE_ + warpM * 64 + mt * 16 + g;
                af[mt][0] = Ab[base];
                af[mt][1] = Ab[base + 8];
                af[mt][2] = Ab[base + 4 * STRIDE_];
                af[mt][3] = Ab[base + 4 * STRIDE_ + 8];
            }
            uint32_t bf[4][2];
            #pragma unroll
            for (int nt = 0; nt < 4; nt++) {
                int base = krow * STRIDE_ + warpN * 8 + nt * 32 + g;
                bf[nt][0] = Bb[base];
                bf[nt][1] = Bb[base + 4 * STRIDE_];
            }
            #pragma unroll
            for (int mt = 0; mt < 4; mt++)
                #pragma unroll
                for (int nt = 0; nt < 4; nt++)
                    mma_tf32(acc[mt][nt], af[mt], bf[nt]);
        }
        __syncthreads();
        if (s < 31) { STORE_TILE((s + 1) & 1); __syncthreads(); }
    }

    // ---- epilogue ----
    // acc[mt][nt][idx]: row = m0 + warpM*64 + mt*16 + g + 8*(idx>>1)
    //                   col = n0 + warpN*8 + nt*32 + 2*tg + (idx&1)
    float bcol[4][2];
    #pragma unroll
    for (int nt = 0; nt < 4; nt++) {
        bcol[nt][0] = bias[n0 + warpN * 8 + nt * 32 + 2 * tg + 0];
        bcol[nt][1] = bias[n0 + warpN * 8 + nt * 32 + 2 * tg + 1];
    }
    #pragma unroll
    for (int mt = 0; mt < 4; mt++)
        #pragma unroll
        for (int nt = 0; nt < 4; nt++) {
            acc[mt][nt][0] += bcol[nt][0];
            acc[mt][nt][1] += bcol[nt][1];
            acc[mt][nt][2] += bcol[nt][0];
            acc[mt][nt][3] += bcol[nt][1];
        }

    if (DO_ROPE) {
        // j = col & 31 = warpN*8 + 2*tg + (idx&1)  (same for both head pairs)
        float sn[2][8], cs[2][8];   // [jj][mt*2 + half]
        #pragma unroll
        for (int jj = 0; jj < 2; jj++) {
            int jcol = warpN * 8 + 2 * tg + jj;
            float invf = (float)exp(-(double)jcol * 0.28782313662425574); // ln(1e4)/32
            #pragma unroll
            for (int mt = 0; mt < 4; mt++)
                #pragma unroll
                for (int half = 0; half < 2; half++) {
                    int row = m0 + warpM * 64 + mt * 16 + g + 8 * half;
                    float sp = (float)(row & (S_ - 1));
                    sincosf(sp * invf, &sn[jj][mt * 2 + half], &cs[jj][mt * 2 + half]);
                }
        }
        // rope pairs: (nt=0, nt=1) and (nt=2, nt=3)
        #pragma unroll
        for (int mt = 0; mt < 4; mt++)
            #pragma unroll
            for (int p = 0; p < 2; p++)
                #pragma unroll
                for (int idx = 0; idx < 4; idx++) {
                    int jj = idx & 1, half = idx >> 1;
                    float c = cs[jj][mt * 2 + half], s = sn[jj][mt * 2 + half];
                    float x1 = acc[mt][2 * p][idx], x2 = acc[mt][2 * p + 1][idx];
                    acc[mt][2 * p][idx]     = x1 * c - x2 * s;
                    acc[mt][2 * p + 1][idx] = x1 * s + x2 * c;
                }
    }

    #pragma unroll
    for (int mt = 0; mt < 4; mt++)
        #pragma unroll
        for (int nt = 0; nt < 4; nt++)
            #pragma unroll
            for (int half = 0; half < 2; half++) {
                int row = m0 + warpM * 64 + mt * 16 + g + 8 * half;
                int col = n0 + warpN * 8 + nt * 32 + 2 * tg;
                float2 ov = { acc[mt][nt][half * 2], acc[mt][nt][half * 2 + 1] };
                *(float2*)(C + (size_t)row * 1024 + col) = ov;
            }
    #undef LOAD_TILE
    #undef STORE_TILE
}

__global__ __launch_bounds__(256)
void qkv_gemm_mma(const float* __restrict__ q, const float* __restrict__ k,
                  const float* __restrict__ v,
                  const float* __restrict__ Wq, const float* __restrict__ bq,
                  const float* __restrict__ Wk, const float* __restrict__ bk,
                  const float* __restrict__ Wv, const float* __restrict__ bv)
{
    if (blockIdx.z == 0)      gemm_mma_body<1>(q, Wq, bq, g_Qp);
    else if (blockIdx.z == 1) gemm_mma_body<1>(k, Wk, bk, g_Kp);
    else                      gemm_mma_body<0>(v, Wv, bv, g_Vp);
}

__global__ __launch_bounds__(256)
void out_gemm_mma(const float* __restrict__ Wo, const float* __restrict__ bo,
                  float* __restrict__ out)
{
    gemm_mma_body<0>(g_Att, Wo, bo, out);
}

// ---------------------------------------------------------------------------
// Causal flash attention (unchanged): 64x64 tiles, 256 threads, 4x4/thread.
// ---------------------------------------------------------------------------
__global__ __launch_bounds__(256) void attn_kernel()
{
    extern __shared__ float sm[];
    float (*Qs)[68] = reinterpret_cast<float(*)[68]>(sm);
    float (*Ks)[68] = reinterpret_cast<float(*)[68]>(sm + 64*68);
    float (*Vs)[68] = reinterpret_cast<float(*)[68]>(sm + 2*64*68);
    float (*Ps)[68] = reinterpret_cast<float(*)[68]>(sm + 3*64*68);

    const int tid = threadIdx.x;
    const int tx = tid & 15, ty = tid >> 4;
    const int qt = (int)(gridDim.x - 1) - (int)blockIdx.x;
    const int h = blockIdx.y, b = blockIdx.z;

    const float* Qb = g_Qp + ((size_t)b * S_ + qt * 64) * D_ + h * 64;
    const float* Kb = g_Kp + (size_t)b * S_ * D_ + h * 64;
    const float* Vb = g_Vp + (size_t)b * S_ * D_ + h * 64;

    #pragma unroll
    for (int t = 0; t < 4; t++) {
        int s4 = tid + t * 256;
        int r  = s4 >> 4;
        int qd = s4 & 15;
        float4 v = *(const float4*)(Qb + (size_t)r * D_ + qd * 4);
        Qs[qd*4+0][r] = v.x; Qs[qd*4+1][r] = v.y;
        Qs[qd*4+2][r] = v.z; Qs[qd*4+3][r] = v.w;
    }

    float m[4], l[4], o[4][4];
    #pragma unroll
    for (int i = 0; i < 4; i++) {
        m[i] = -INFINITY; l[i] = 0.f;
        #pragma unroll
        for (int j = 0; j < 4; j++) o[i][j] = 0.f;
    }

    for (int kt = 0; kt <= qt; kt++) {
        __syncthreads();
        #pragma unroll
        for (int t = 0; t < 4; t++) {
            int s4 = tid + t * 256;
            int r  = s4 >> 4, qd = s4 & 15;
            const float* Kr = Kb + ((size_t)(kt * 64 + r)) * D_;
            float4 kv = *(const float4*)(Kr + qd * 4);
            Ks[qd*4+0][r] = kv.x; Ks[qd*4+1][r] = kv.y;
            Ks[qd*4+2][r] = kv.z; Ks[qd*4+3][r] = kv.w;
            const float* Vr = Vb + ((size_t)(kt * 64 + r)) * D_;
            *(float4*)&Vs[r][qd*4] = *(const float4*)(Vr + qd * 4);
        }
        __syncthreads();

        float sv[4][4];
        #pragma unroll
        for (int i = 0; i < 4; i++)
            #pragma unroll
            for (int j = 0; j < 4; j++) sv[i][j] = 0.f;

        #pragma unroll 16
        for (int d = 0; d < 64; d++) {
            float4 qv = *(const float4*)&Qs[d][ty*4];
            float4 kv = *(const float4*)&Ks[d][tx*4];
            float aa[4] = {qv.x, qv.y, qv.z, qv.w};
            float bb[4] = {kv.x, kv.y, kv.z, kv.w};
            #pragma unroll
            for (int ii = 0; ii < 4; ii++)
                #pragma unroll
                for (int jj = 0; jj < 4; jj++)
                    sv[ii][jj] = fmaf(aa[ii], bb[jj], sv[ii][jj]);
        }

        const float scale = 0.125f;
        const bool diag = (kt == qt);

        #pragma unroll
        for (int ii = 0; ii < 4; ii++) {
            int qi = qt * 64 + ty * 4 + ii;
            float rm = -INFINITY;
            #pragma unroll
            for (int jj = 0; jj < 4; jj++) {
                float x = sv[ii][jj] * scale;
                if (diag && (kt * 64 + tx * 4 + jj) > qi) x = -INFINITY;
                sv[ii][jj] = x;
                rm = fmaxf(rm, x);
            }
            #pragma unroll
            for (int off = 1; off < 16; off <<= 1)
                rm = fmaxf(rm, __shfl_xor_sync(0xffffffffu, rm, off));
            float mn = fmaxf(m[ii], rm);
            float alpha = __expf(m[ii] - mn);
            float rs = 0.f;
            #pragma unroll
            for (int jj = 0; jj < 4; jj++) {
                float p = __expf(sv[ii][jj] - mn);
                sv[ii][jj] = p; rs += p;
            }
            #pragma unroll
            for (int off = 1; off < 16; off <<= 1)
                rs += __shfl_xor_sync(0xffffffffu, rs, off);
            l[ii] = l[ii] * alpha + rs;
            m[ii] = mn;
            #pragma unroll
            for (int jj = 0; jj < 4; jj++) o[ii][jj] *= alpha;
        }

        #pragma unroll
        for (int ii = 0; ii < 4; ii++)
            #pragma unroll
            for (int jj = 0; jj < 4; jj++)
                Ps[tx*4+jj][ty*4+ii] = sv[ii][jj];
        __syncthreads();

        #pragma unroll 16
        for (int j = 0; j < 64; j++) {
            float4 pv = *(const float4*)&Ps[j][ty*4];
            float4 vv = *(const float4*)&Vs[j][tx*4];
            float pa[4] = {pv.x, pv.y, pv.z, pv.w};
            float vb4[4] = {vv.x, vv.y, vv.z, vv.w};
            #pragma unroll
            for (int ii = 0; ii < 4; ii++)
                #pragma unroll
                for (int jj = 0; jj < 4; jj++)
                    o[ii][jj] = fmaf(pa[ii], vb4[jj], o[ii][jj]);
        }
    }

    float* Ob = g_Att + ((size_t)b * S_ + qt * 64) * D_ + h * 64;
    #pragma unroll
    for (int ii = 0; ii < 4; ii++) {
        float inv = 1.0f / l[ii];
        float4 ov = { o[ii][0]*inv, o[ii][1]*inv, o[ii][2]*inv, o[ii][3]*inv };
        *(float4*)(Ob + (size_t)(ty*4+ii) * D_ + tx*4) = ov;
    }
}

// ---------------------------------------------------------------------------
extern "C" void kernel_launch(void* const* d_in, const int* in_sizes, int n_in,
                              void* d_out, int out_size)
{
    (void)in_sizes; (void)n_in; (void)out_size;
    const float* q  = (const float*)d_in[0];
    const float* k  = (const float*)d_in[1];
    const float* v  = (const float*)d_in[2];
    const float* Wq = (const float*)d_in[4];
    const float* bq = (const float*)d_in[5];
    const float* Wk = (const float*)d_in[6];
    const float* bk = (const float*)d_in[7];
    const float* Wv = (const float*)d_in[8];
    const float* bv = (const float*)d_in[9];
    const float* Wo = (const float*)d_in[10];
    const float* bo = (const float*)d_in[11];
    float* out = (float*)d_out;

    const int gemm_smem = 4 * STAGE_WORDS_ * 4;      // 67584 B
    cudaFuncSetAttribute(qkv_gemm_mma, cudaFuncAttributeMaxDynamicSharedMemorySize, gemm_smem);
    cudaFuncSetAttribute(out_gemm_mma, cudaFuncAttributeMaxDynamicSharedMemorySize, gemm_smem);
    const int attn_smem = 4 * 64 * 68 * 4;           // 69632 B
    cudaFuncSetAttribute(attn_kernel, cudaFuncAttributeMaxDynamicSharedMemorySize, attn_smem);

    dim3 gqkv(1024/128, M_/128, 3);
    qkv_gemm_mma<<<gqkv, 256, gemm_smem>>>(q, k, v, Wq, bq, Wk, bk, Wv, bv);

    attn_kernel<<<dim3(S_/64, H_, B_), 256, attn_smem>>>();

    out_gemm_mma<<<dim3(1024/128, M_/128), 256, gemm_smem>>>(Wo, bo, out);
}

// round 4
// speedup vs baseline: 1.5537x; 1.0933x over previous
#include <cuda_runtime.h>
#include <math.h>
#include <stdint.h>

#define B_ 2
#define S_ 2048
#define D_ 1024
#define H_ 16
#define M_ (B_*S_)

// Scratch (allocation-free rule: __device__ globals)
__device__ float g_Qp[(size_t)B_*S_*D_];
__device__ float g_Kp[(size_t)B_*S_*D_];
__device__ float g_Vp[(size_t)B_*S_*D_];
__device__ float g_Att[(size_t)B_*S_*D_];

__device__ __forceinline__ uint32_t f2tf32(float x) {
    uint32_t r;
    asm("cvt.rna.tf32.f32 %0, %1;" : "=r"(r) : "f"(x));
    return r;
}

__device__ __forceinline__ void mma_tf32(float* d, const uint32_t* a, const uint32_t* b) {
    asm volatile(
        "mma.sync.aligned.m16n8k8.row.col.f32.tf32.tf32.f32 "
        "{%0,%1,%2,%3}, {%4,%5,%6,%7}, {%8,%9}, {%0,%1,%2,%3};"
        : "+f"(d[0]), "+f"(d[1]), "+f"(d[2]), "+f"(d[3])
        : "r"(a[0]), "r"(a[1]), "r"(a[2]), "r"(a[3]), "r"(b[0]), "r"(b[1]));
}

// ---------------------------------------------------------------------------
// tf32 mma.sync GEMM (unchanged from round 3, passing)
// ---------------------------------------------------------------------------
#define STRIDE_ 132
#define STAGE_WORDS_ (32*STRIDE_)

template<int DO_ROPE>
__device__ __forceinline__ void gemm_mma_body(const float* __restrict__ A,
                                              const float* __restrict__ W,
                                              const float* __restrict__ bias,
                                              float* __restrict__ C)
{
    extern __shared__ uint32_t sm_[];
    uint32_t* As = sm_;
    uint32_t* Bs = sm_ + 2 * STAGE_WORDS_;

    const int tid  = threadIdx.x;
    const int lane = tid & 31, w = tid >> 5;
    const int warpM = w & 1, warpN = w >> 1;
    const int g = lane >> 2, tg = lane & 3;
    const int m0 = blockIdx.y * 128, n0 = blockIdx.x * 128;

    const int rbase = 8 * (w & 3) + g;
    const int q     = (lane & 3) + 4 * (w >> 2);

    float4 ra[4], rb[4];
    #define LOAD_TILE(k0_)                                                     \
        _Pragma("unroll")                                                      \
        for (int t = 0; t < 4; t++) {                                          \
            int r = rbase + 32 * t;                                            \
            ra[t] = *(const float4*)(A + (size_t)(m0 + r) * 1024 + (k0_) + q * 4); \
            rb[t] = *(const float4*)(W + (size_t)(n0 + r) * 1024 + (k0_) + q * 4); \
        }
    #define STORE_TILE(buf_)                                                   \
        _Pragma("unroll")                                                      \
        for (int t = 0; t < 4; t++) {                                          \
            int r = rbase + 32 * t;                                            \
            uint32_t* Ad = As + (buf_) * STAGE_WORDS_ + r;                     \
            uint32_t* Bd = Bs + (buf_) * STAGE_WORDS_ + r;                     \
            Ad[(4*q+0)*STRIDE_] = f2tf32(ra[t].x);                             \
            Ad[(4*q+1)*STRIDE_] = f2tf32(ra[t].y);                             \
            Ad[(4*q+2)*STRIDE_] = f2tf32(ra[t].z);                             \
            Ad[(4*q+3)*STRIDE_] = f2tf32(ra[t].w);                             \
            Bd[(4*q+0)*STRIDE_] = f2tf32(rb[t].x);                             \
            Bd[(4*q+1)*STRIDE_] = f2tf32(rb[t].y);                             \
            Bd[(4*q+2)*STRIDE_] = f2tf32(rb[t].z);                             \
            Bd[(4*q+3)*STRIDE_] = f2tf32(rb[t].w);                             \
        }

    float acc[4][4][4];
    #pragma unroll
    for (int i = 0; i < 4; i++)
        #pragma unroll
        for (int j = 0; j < 4; j++)
            #pragma unroll
            for (int x = 0; x < 4; x++) acc[i][j][x] = 0.f;

    LOAD_TILE(0);
    STORE_TILE(0);
    __syncthreads();

    #pragma unroll 1
    for (int s = 0; s < 32; s++) {
        if (s < 31) { LOAD_TILE((s + 1) * 32); }

        const uint32_t* Ab = As + (s & 1) * STAGE_WORDS_;
        const uint32_t* Bb = Bs + (s & 1) * STAGE_WORDS_;
        #pragma unroll
        for (int ks = 0; ks < 4; ks++) {
            const int krow = ks * 8 + tg;
            uint32_t af[4][4];
            #pragma unroll
            for (int mt = 0; mt < 4; mt++) {
                int base = krow * STRIDE_ + warpM * 64 + mt * 16 + g;
                af[mt][0] = Ab[base];
                af[mt][1] = Ab[base + 8];
                af[mt][2] = Ab[base + 4 * STRIDE_];
                af[mt][3] = Ab[base + 4 * STRIDE_ + 8];
            }
            uint32_t bf[4][2];
            #pragma unroll
            for (int nt = 0; nt < 4; nt++) {
                int base = krow * STRIDE_ + warpN * 8 + nt * 32 + g;
                bf[nt][0] = Bb[base];
                bf[nt][1] = Bb[base + 4 * STRIDE_];
            }
            #pragma unroll
            for (int mt = 0; mt < 4; mt++)
                #pragma unroll
                for (int nt = 0; nt < 4; nt++)
                    mma_tf32(acc[mt][nt], af[mt], bf[nt]);
        }
        __syncthreads();
        if (s < 31) { STORE_TILE((s + 1) & 1); __syncthreads(); }
    }

    float bcol[4][2];
    #pragma unroll
    for (int nt = 0; nt < 4; nt++) {
        bcol[nt][0] = bias[n0 + warpN * 8 + nt * 32 + 2 * tg + 0];
        bcol[nt][1] = bias[n0 + warpN * 8 + nt * 32 + 2 * tg + 1];
    }
    #pragma unroll
    for (int mt = 0; mt < 4; mt++)
        #pragma unroll
        for (int nt = 0; nt < 4; nt++) {
            acc[mt][nt][0] += bcol[nt][0];
            acc[mt][nt][1] += bcol[nt][1];
            acc[mt][nt][2] += bcol[nt][0];
            acc[mt][nt][3] += bcol[nt][1];
        }

    if (DO_ROPE) {
        float sn[2][8], cs[2][8];
        #pragma unroll
        for (int jj = 0; jj < 2; jj++) {
            int jcol = warpN * 8 + 2 * tg + jj;
            float invf = (float)exp(-(double)jcol * 0.28782313662425574);
            #pragma unroll
            for (int mt = 0; mt < 4; mt++)
                #pragma unroll
                for (int half = 0; half < 2; half++) {
                    int row = m0 + warpM * 64 + mt * 16 + g + 8 * half;
                    float sp = (float)(row & (S_ - 1));
                    sincosf(sp * invf, &sn[jj][mt * 2 + half], &cs[jj][mt * 2 + half]);
                }
        }
        #pragma unroll
        for (int mt = 0; mt < 4; mt++)
            #pragma unroll
            for (int p = 0; p < 2; p++)
                #pragma unroll
                for (int idx = 0; idx < 4; idx++) {
                    int jj = idx & 1, half = idx >> 1;
                    float c = cs[jj][mt * 2 + half], s = sn[jj][mt * 2 + half];
                    float x1 = acc[mt][2 * p][idx], x2 = acc[mt][2 * p + 1][idx];
                    acc[mt][2 * p][idx]     = x1 * c - x2 * s;
                    acc[mt][2 * p + 1][idx] = x1 * s + x2 * c;
                }
    }

    #pragma unroll
    for (int mt = 0; mt < 4; mt++)
        #pragma unroll
        for (int nt = 0; nt < 4; nt++)
            #pragma unroll
            for (int half = 0; half < 2; half++) {
                int row = m0 + warpM * 64 + mt * 16 + g + 8 * half;
                int col = n0 + warpN * 8 + nt * 32 + 2 * tg;
                float2 ov = { acc[mt][nt][half * 2], acc[mt][nt][half * 2 + 1] };
                *(float2*)(C + (size_t)row * 1024 + col) = ov;
            }
    #undef LOAD_TILE
    #undef STORE_TILE
}

__global__ __launch_bounds__(256)
void qkv_gemm_mma(const float* __restrict__ q, const float* __restrict__ k,
                  const float* __restrict__ v,
                  const float* __restrict__ Wq, const float* __restrict__ bq,
                  const float* __restrict__ Wk, const float* __restrict__ bk,
                  const float* __restrict__ Wv, const float* __restrict__ bv)
{
    if (blockIdx.z == 0)      gemm_mma_body<1>(q, Wq, bq, g_Qp);
    else if (blockIdx.z == 1) gemm_mma_body<1>(k, Wk, bk, g_Kp);
    else                      gemm_mma_body<0>(v, Wv, bv, g_Vp);
}

__global__ __launch_bounds__(256)
void out_gemm_mma(const float* __restrict__ Wo, const float* __restrict__ bo,
                  float* __restrict__ out)
{
    gemm_mma_body<0>(g_Att, Wo, bo, out);
}

// ---------------------------------------------------------------------------
// Causal flash attention with tf32 mma.sync.
// CTA: 128 threads (4 warps), 64 q-rows (warp = 16 rows), DK=64.
// S = QK^T via 3xTF32 (hi/lo split, Q pre-scaled by 1/8). PV via plain tf32.
// smem u32 words, stride 68:
//   Qhi[64d][64q] Qlo | Khi[64d][64k] Klo | Vs[64k][64d] | Ps[64k][64q]
// ---------------------------------------------------------------------------
#define AST_ 68
__global__ __launch_bounds__(128) void attn_kernel()
{
    extern __shared__ uint32_t asm_[];
    uint32_t* Qhi = asm_;
    uint32_t* Qlo = asm_ + 1 * 64 * AST_;
    uint32_t* Khi = asm_ + 2 * 64 * AST_;
    uint32_t* Klo = asm_ + 3 * 64 * AST_;
    uint32_t* Vs  = asm_ + 4 * 64 * AST_;
    uint32_t* Ps  = asm_ + 5 * 64 * AST_;

    const int tid = threadIdx.x;
    const int lane = tid & 31, w = tid >> 5;
    const int g = lane >> 2, tg = lane & 3;
    const int qt = (int)(gridDim.x - 1) - (int)blockIdx.x;   // heavy first
    const int h = blockIdx.y, b = blockIdx.z;

    const float* Qb = g_Qp + ((size_t)b * S_ + qt * 64) * D_ + h * 64;
    const float* Kb = g_Kp + (size_t)b * S_ * D_ + h * 64;
    const float* Vb = g_Vp + (size_t)b * S_ * D_ + h * 64;

    // loader mapping: thread -> (row = tid>>1, quads (tid&1)*8 .. +7)
    const int lrow = tid >> 1;
    const int lqb  = (tid & 1) * 8;

    // ---- load Q once (pre-scaled by 1/8, hi/lo split, [d][qrow]) ----
    #pragma unroll
    for (int qq = 0; qq < 8; qq++) {
        int d0 = (lqb + qq) * 4;
        float4 qv = *(const float4*)(Qb + (size_t)lrow * D_ + d0);
        float xv[4] = {qv.x, qv.y, qv.z, qv.w};
        #pragma unroll
        for (int i = 0; i < 4; i++) {
            float x = xv[i] * 0.125f;
            uint32_t hi = f2tf32(x);
            uint32_t lo = f2tf32(x - __uint_as_float(hi));
            Qhi[(d0 + i) * AST_ + lrow] = hi;
            Qlo[(d0 + i) * AST_ + lrow] = lo;
        }
    }

    float m[2], l[2], o[8][4];
    m[0] = m[1] = -INFINITY; l[0] = l[1] = 0.f;
    #pragma unroll
    for (int nt = 0; nt < 8; nt++)
        #pragma unroll
        for (int c = 0; c < 4; c++) o[nt][c] = 0.f;

    #pragma unroll 1
    for (int kt = 0; kt <= qt; kt++) {
        __syncthreads();   // K/V buffers free
        #pragma unroll
        for (int qq = 0; qq < 8; qq++) {
            int d0 = (lqb + qq) * 4;
            const float* Kr = Kb + ((size_t)(kt * 64 + lrow)) * D_;
            float4 kv = *(const float4*)(Kr + d0);
            float xv[4] = {kv.x, kv.y, kv.z, kv.w};
            #pragma unroll
            for (int i = 0; i < 4; i++) {
                uint32_t hi = f2tf32(xv[i]);
                uint32_t lo = f2tf32(xv[i] - __uint_as_float(hi));
                Khi[(d0 + i) * AST_ + lrow] = hi;
                Klo[(d0 + i) * AST_ + lrow] = lo;
            }
            const float* Vr = Vb + ((size_t)(kt * 64 + lrow)) * D_;
            float4 vv = *(const float4*)(Vr + d0);
            uint4 tv = { f2tf32(vv.x), f2tf32(vv.y), f2tf32(vv.z), f2tf32(vv.w) };
            *(uint4*)&Vs[lrow * AST_ + d0] = tv;
        }
        __syncthreads();

        // ---- S = Q K^T (3xTF32) ----
        float sacc[8][4];
        #pragma unroll
        for (int nt = 0; nt < 8; nt++)
            #pragma unroll
            for (int c = 0; c < 4; c++) sacc[nt][c] = 0.f;

        #pragma unroll
        for (int ks = 0; ks < 8; ks++) {
            const int kr = ks * 8 + tg;
            const int abase = kr * AST_ + w * 16 + g;
            uint32_t ahi[4], alo[4];
            ahi[0] = Qhi[abase];               alo[0] = Qlo[abase];
            ahi[1] = Qhi[abase + 8];           alo[1] = Qlo[abase + 8];
            ahi[2] = Qhi[abase + 4 * AST_];    alo[2] = Qlo[abase + 4 * AST_];
            ahi[3] = Qhi[abase + 4 * AST_ + 8];alo[3] = Qlo[abase + 4 * AST_ + 8];
            #pragma unroll
            for (int nt = 0; nt < 8; nt++) {
                const int bbase = kr * AST_ + nt * 8 + g;
                uint32_t bhi[2], blo[2];
                bhi[0] = Khi[bbase];            bhi[1] = Khi[bbase + 4 * AST_];
                blo[0] = Klo[bbase];            blo[1] = Klo[bbase + 4 * AST_];
                mma_tf32(sacc[nt], ahi, bhi);
                mma_tf32(sacc[nt], ahi, blo);
                mma_tf32(sacc[nt], alo, bhi);
            }
        }

        // ---- masking (diag tile only) ----
        if (kt == qt) {
            #pragma unroll
            for (int nt = 0; nt < 8; nt++)
                #pragma unroll
                for (int c = 0; c < 4; c++) {
                    int colL = nt * 8 + 2 * tg + (c & 1);
                    int rowL = w * 16 + g + 8 * (c >> 1);
                    if (colL > rowL) sacc[nt][c] = -INFINITY;
                }
        }

        // ---- online softmax (rows g, g+8; stats replicated over tg quad) ----
        float rm[2] = {-INFINITY, -INFINITY};
        #pragma unroll
        for (int nt = 0; nt < 8; nt++) {
            rm[0] = fmaxf(rm[0], fmaxf(sacc[nt][0], sacc[nt][1]));
            rm[1] = fmaxf(rm[1], fmaxf(sacc[nt][2], sacc[nt][3]));
        }
        #pragma unroll
        for (int r = 0; r < 2; r++) {
            rm[r] = fmaxf(rm[r], __shfl_xor_sync(0xffffffffu, rm[r], 1));
            rm[r] = fmaxf(rm[r], __shfl_xor_sync(0xffffffffu, rm[r], 2));
        }
        float alpha[2], rs[2];
        #pragma unroll
        for (int r = 0; r < 2; r++) {
            float mn = fmaxf(m[r], rm[r]);
            alpha[r] = __expf(m[r] - mn);
            m[r] = mn;
            rs[r] = 0.f;
        }
        #pragma unroll
        for (int nt = 0; nt < 8; nt++) {
            #pragma unroll
            for (int c = 0; c < 4; c++) {
                int r = c >> 1;
                float p = __expf(sacc[nt][c] - m[r]);
                sacc[nt][c] = p;
                rs[r] += p;
            }
        }
        #pragma unroll
        for (int r = 0; r < 2; r++) {
            rs[r] += __shfl_xor_sync(0xffffffffu, rs[r], 1);
            rs[r] += __shfl_xor_sync(0xffffffffu, rs[r], 2);
            l[r] = l[r] * alpha[r] + rs[r];
        }
        #pragma unroll
        for (int nt = 0; nt < 8; nt++) {
            o[nt][0] *= alpha[0]; o[nt][1] *= alpha[0];
            o[nt][2] *= alpha[1]; o[nt][3] *= alpha[1];
        }

        // ---- store P^T [kpos][qrow] (warp-private rows) ----
        #pragma unroll
        for (int nt = 0; nt < 8; nt++)
            #pragma unroll
            for (int c = 0; c < 4; c++) {
                int kpos = nt * 8 + 2 * tg + (c & 1);
                int qrow = w * 16 + g + 8 * (c >> 1);
                Ps[kpos * AST_ + qrow] = f2tf32(sacc[nt][c]);
            }
        __syncwarp();

        // ---- O += P V ----
        #pragma unroll
        for (int ks = 0; ks < 8; ks++) {
            const int kr = ks * 8 + tg;
            const int abase = kr * AST_ + w * 16 + g;
            uint32_t pa[4];
            pa[0] = Ps[abase];
            pa[1] = Ps[abase + 8];
            pa[2] = Ps[abase + 4 * AST_];
            pa[3] = Ps[abase + 4 * AST_ + 8];
            #pragma unroll
            for (int nt = 0; nt < 8; nt++) {
                const int bbase = kr * AST_ + nt * 8 + g;
                uint32_t vb[2];
                vb[0] = Vs[bbase];
                vb[1] = Vs[bbase + 4 * AST_];
                mma_tf32(o[nt], pa, vb);
            }
        }
    }

    // ---- finalize & store ----
    float inv[2] = { 1.0f / l[0], 1.0f / l[1] };
    float* Ob = g_Att + ((size_t)b * S_ + qt * 64) * D_ + h * 64;
    #pragma unroll
    for (int nt = 0; nt < 8; nt++)
        #pragma unroll
        for (int r = 0; r < 2; r++) {
            int row = w * 16 + g + 8 * r;
            int col = nt * 8 + 2 * tg;
            float2 ov = { o[nt][2 * r] * inv[r], o[nt][2 * r + 1] * inv[r] };
            *(float2*)(Ob + (size_t)row * D_ + col) = ov;
        }
}

// ---------------------------------------------------------------------------
extern "C" void kernel_launch(void* const* d_in, const int* in_sizes, int n_in,
                              void* d_out, int out_size)
{
    (void)in_sizes; (void)n_in; (void)out_size;
    const float* q  = (const float*)d_in[0];
    const float* k  = (const float*)d_in[1];
    const float* v  = (const float*)d_in[2];
    const float* Wq = (const float*)d_in[4];
    const float* bq = (const float*)d_in[5];
    const float* Wk = (const float*)d_in[6];
    const float* bk = (const float*)d_in[7];
    const float* Wv = (const float*)d_in[8];
    const float* bv = (const float*)d_in[9];
    const float* Wo = (const float*)d_in[10];
    const float* bo = (const float*)d_in[11];
    float* out = (float*)d_out;

    const int gemm_smem = 4 * STAGE_WORDS_ * 4;      // 67584 B
    cudaFuncSetAttribute(qkv_gemm_mma, cudaFuncAttributeMaxDynamicSharedMemorySize, gemm_smem);
    cudaFuncSetAttribute(out_gemm_mma, cudaFuncAttributeMaxDynamicSharedMemorySize, gemm_smem);
    const int attn_smem = 6 * 64 * AST_ * 4;         // 104448 B
    cudaFuncSetAttribute(attn_kernel, cudaFuncAttributeMaxDynamicSharedMemorySize, attn_smem);

    dim3 gqkv(1024/128, M_/128, 3);
    qkv_gemm_mma<<<gqkv, 256, gemm_smem>>>(q, k, v, Wq, bq, Wk, bk, Wv, bv);

    attn_kernel<<<dim3(S_/64, H_, B_), 128, attn_smem>>>();

    out_gemm_mma<<<dim3(1024/128, M_/128), 256, gemm_smem>>>(Wo, bo, out);
}

// round 5
// speedup vs baseline: 1.8531x; 1.1927x over previous
#include <cuda_runtime.h>
#include <math.h>
#include <stdint.h>

#define B_ 2
#define S_ 2048
#define D_ 1024
#define H_ 16
#define M_ (B_*S_)

// Scratch (allocation-free rule: __device__ globals)
__device__ float g_Qp[(size_t)B_*S_*D_];
__device__ float g_Kp[(size_t)B_*S_*D_];
__device__ float g_Vp[(size_t)B_*S_*D_];
__device__ float g_Att[(size_t)B_*S_*D_];

__device__ __forceinline__ uint32_t f2tf32(float x) {
    uint32_t r;
    asm("cvt.rna.tf32.f32 %0, %1;" : "=r"(r) : "f"(x));
    return r;
}

__device__ __forceinline__ void mma_tf32(float* d, const uint32_t* a, const uint32_t* b) {
    asm volatile(
        "mma.sync.aligned.m16n8k8.row.col.f32.tf32.tf32.f32 "
        "{%0,%1,%2,%3}, {%4,%5,%6,%7}, {%8,%9}, {%0,%1,%2,%3};"
        : "+f"(d[0]), "+f"(d[1]), "+f"(d[2]), "+f"(d[3])
        : "r"(a[0]), "r"(a[1]), "r"(a[2]), "r"(a[3]), "r"(b[0]), "r"(b[1]));
}

// ---------------------------------------------------------------------------
// tf32 mma.sync GEMM (unchanged, passing)
// ---------------------------------------------------------------------------
#define STRIDE_ 132
#define STAGE_WORDS_ (32*STRIDE_)

template<int DO_ROPE>
__device__ __forceinline__ void gemm_mma_body(const float* __restrict__ A,
                                              const float* __restrict__ W,
                                              const float* __restrict__ bias,
                                              float* __restrict__ C)
{
    extern __shared__ uint32_t sm_[];
    uint32_t* As = sm_;
    uint32_t* Bs = sm_ + 2 * STAGE_WORDS_;

    const int tid  = threadIdx.x;
    const int lane = tid & 31, w = tid >> 5;
    const int warpM = w & 1, warpN = w >> 1;
    const int g = lane >> 2, tg = lane & 3;
    const int m0 = blockIdx.y * 128, n0 = blockIdx.x * 128;

    const int rbase = 8 * (w & 3) + g;
    const int q     = (lane & 3) + 4 * (w >> 2);

    float4 ra[4], rb[4];
    #define LOAD_TILE(k0_)                                                     \
        _Pragma("unroll")                                                      \
        for (int t = 0; t < 4; t++) {                                          \
            int r = rbase + 32 * t;                                            \
            ra[t] = *(const float4*)(A + (size_t)(m0 + r) * 1024 + (k0_) + q * 4); \
            rb[t] = *(const float4*)(W + (size_t)(n0 + r) * 1024 + (k0_) + q * 4); \
        }
    #define STORE_TILE(buf_)                                                   \
        _Pragma("unroll")                                                      \
        for (int t = 0; t < 4; t++) {                                          \
            int r = rbase + 32 * t;                                            \
            uint32_t* Ad = As + (buf_) * STAGE_WORDS_ + r;                     \
            uint32_t* Bd = Bs + (buf_) * STAGE_WORDS_ + r;                     \
            Ad[(4*q+0)*STRIDE_] = f2tf32(ra[t].x);                             \
            Ad[(4*q+1)*STRIDE_] = f2tf32(ra[t].y);                             \
            Ad[(4*q+2)*STRIDE_] = f2tf32(ra[t].z);                             \
            Ad[(4*q+3)*STRIDE_] = f2tf32(ra[t].w);                             \
            Bd[(4*q+0)*STRIDE_] = f2tf32(rb[t].x);                             \
            Bd[(4*q+1)*STRIDE_] = f2tf32(rb[t].y);                             \
            Bd[(4*q+2)*STRIDE_] = f2tf32(rb[t].z);                             \
            Bd[(4*q+3)*STRIDE_] = f2tf32(rb[t].w);                             \
        }

    float acc[4][4][4];
    #pragma unroll
    for (int i = 0; i < 4; i++)
        #pragma unroll
        for (int j = 0; j < 4; j++)
            #pragma unroll
            for (int x = 0; x < 4; x++) acc[i][j][x] = 0.f;

    LOAD_TILE(0);
    STORE_TILE(0);
    __syncthreads();

    #pragma unroll 1
    for (int s = 0; s < 32; s++) {
        if (s < 31) { LOAD_TILE((s + 1) * 32); }

        const uint32_t* Ab = As + (s & 1) * STAGE_WORDS_;
        const uint32_t* Bb = Bs + (s & 1) * STAGE_WORDS_;
        #pragma unroll
        for (int ks = 0; ks < 4; ks++) {
            const int krow = ks * 8 + tg;
            uint32_t af[4][4];
            #pragma unroll
            for (int mt = 0; mt < 4; mt++) {
                int base = krow * STRIDE_ + warpM * 64 + mt * 16 + g;
                af[mt][0] = Ab[base];
                af[mt][1] = Ab[base + 8];
                af[mt][2] = Ab[base + 4 * STRIDE_];
                af[mt][3] = Ab[base + 4 * STRIDE_ + 8];
            }
            uint32_t bf[4][2];
            #pragma unroll
            for (int nt = 0; nt < 4; nt++) {
                int base = krow * STRIDE_ + warpN * 8 + nt * 32 + g;
                bf[nt][0] = Bb[base];
                bf[nt][1] = Bb[base + 4 * STRIDE_];
            }
            #pragma unroll
            for (int mt = 0; mt < 4; mt++)
                #pragma unroll
                for (int nt = 0; nt < 4; nt++)
                    mma_tf32(acc[mt][nt], af[mt], bf[nt]);
        }
        __syncthreads();
        if (s < 31) { STORE_TILE((s + 1) & 1); __syncthreads(); }
    }

    float bcol[4][2];
    #pragma unroll
    for (int nt = 0; nt < 4; nt++) {
        bcol[nt][0] = bias[n0 + warpN * 8 + nt * 32 + 2 * tg + 0];
        bcol[nt][1] = bias[n0 + warpN * 8 + nt * 32 + 2 * tg + 1];
    }
    #pragma unroll
    for (int mt = 0; mt < 4; mt++)
        #pragma unroll
        for (int nt = 0; nt < 4; nt++) {
            acc[mt][nt][0] += bcol[nt][0];
            acc[mt][nt][1] += bcol[nt][1];
            acc[mt][nt][2] += bcol[nt][0];
            acc[mt][nt][3] += bcol[nt][1];
        }

    if (DO_ROPE) {
        float sn[2][8], cs[2][8];
        #pragma unroll
        for (int jj = 0; jj < 2; jj++) {
            int jcol = warpN * 8 + 2 * tg + jj;
            float invf = (float)exp(-(double)jcol * 0.28782313662425574);
            #pragma unroll
            for (int mt = 0; mt < 4; mt++)
                #pragma unroll
                for (int half = 0; half < 2; half++) {
                    int row = m0 + warpM * 64 + mt * 16 + g + 8 * half;
                    float sp = (float)(row & (S_ - 1));
                    sincosf(sp * invf, &sn[jj][mt * 2 + half], &cs[jj][mt * 2 + half]);
                }
        }
        #pragma unroll
        for (int mt = 0; mt < 4; mt++)
            #pragma unroll
            for (int p = 0; p < 2; p++)
                #pragma unroll
                for (int idx = 0; idx < 4; idx++) {
                    int jj = idx & 1, half = idx >> 1;
                    float c = cs[jj][mt * 2 + half], s = sn[jj][mt * 2 + half];
                    float x1 = acc[mt][2 * p][idx], x2 = acc[mt][2 * p + 1][idx];
                    acc[mt][2 * p][idx]     = x1 * c - x2 * s;
                    acc[mt][2 * p + 1][idx] = x1 * s + x2 * c;
                }
    }

    #pragma unroll
    for (int mt = 0; mt < 4; mt++)
        #pragma unroll
        for (int nt = 0; nt < 4; nt++)
            #pragma unroll
            for (int half = 0; half < 2; half++) {
                int row = m0 + warpM * 64 + mt * 16 + g + 8 * half;
                int col = n0 + warpN * 8 + nt * 32 + 2 * tg;
                float2 ov = { acc[mt][nt][half * 2], acc[mt][nt][half * 2 + 1] };
                *(float2*)(C + (size_t)row * 1024 + col) = ov;
            }
    #undef LOAD_TILE
    #undef STORE_TILE
}

__global__ __launch_bounds__(256)
void qkv_gemm_mma(const float* __restrict__ q, const float* __restrict__ k,
                  const float* __restrict__ v,
                  const float* __restrict__ Wq, const float* __restrict__ bq,
                  const float* __restrict__ Wk, const float* __restrict__ bk,
                  const float* __restrict__ Wv, const float* __restrict__ bv)
{
    if (blockIdx.z == 0)      gemm_mma_body<1>(q, Wq, bq, g_Qp);
    else if (blockIdx.z == 1) gemm_mma_body<1>(k, Wk, bk, g_Kp);
    else                      gemm_mma_body<0>(v, Wv, bv, g_Vp);
}

__global__ __launch_bounds__(256)
void out_gemm_mma(const float* __restrict__ Wo, const float* __restrict__ bo,
                  float* __restrict__ out)
{
    gemm_mma_body<0>(g_Att, Wo, bo, out);
}

// ---------------------------------------------------------------------------
// Causal flash attention, v2: 128 threads, 64x64 tiles, 2xTF32 scores.
//  - Qs: tf32 [q][d]   (Q pre-scaled 1/8; dropping q_lo term ~1.4e-4 score err)
//  - Kf: fp32 [k][d]   (split hi/lo in registers at fragment load)
//  - Vs: tf32 [d][k]   (transposed -> conflict-free vb loads)
//  - Ps: tf32 [k][q]
// smem = 4 * 64*68*4 = 69632 B -> 3 CTAs/SM (12 warps).
// ---------------------------------------------------------------------------
#define AST_ 68
__global__ __launch_bounds__(128, 3) void attn_kernel()
{
    extern __shared__ uint32_t asm_[];
    uint32_t* Qs = asm_;
    float*    Kf = (float*)(asm_ + 1 * 64 * AST_);
    uint32_t* Vs = asm_ + 2 * 64 * AST_;
    uint32_t* Ps = asm_ + 3 * 64 * AST_;

    const int tid = threadIdx.x;
    const int lane = tid & 31, w = tid >> 5;
    const int g = lane >> 2, tg = lane & 3;
    const int qt = (int)(gridDim.x - 1) - (int)blockIdx.x;   // heavy first
    const int h = blockIdx.y, b = blockIdx.z;

    const float* Qb = g_Qp + ((size_t)b * S_ + qt * 64) * D_ + h * 64;
    const float* Kb = g_Kp + (size_t)b * S_ * D_ + h * 64;
    const float* Vb = g_Vp + (size_t)b * S_ * D_ + h * 64;

    const int lrow = tid >> 1;
    const int lqb  = (tid & 1) * 8;

    // ---- load Q once: scale 1/8, tf32, [q][d] ----
    #pragma unroll
    for (int qq = 0; qq < 8; qq++) {
        int d0 = (lqb + qq) * 4;
        float4 qv = *(const float4*)(Qb + (size_t)lrow * D_ + d0);
        uint4 tq = { f2tf32(qv.x * 0.125f), f2tf32(qv.y * 0.125f),
                     f2tf32(qv.z * 0.125f), f2tf32(qv.w * 0.125f) };
        *(uint4*)&Qs[lrow * AST_ + d0] = tq;
    }

    float m[2], l[2], o[8][4];
    m[0] = m[1] = -INFINITY; l[0] = l[1] = 0.f;
    #pragma unroll
    for (int nt = 0; nt < 8; nt++)
        #pragma unroll
        for (int c = 0; c < 4; c++) o[nt][c] = 0.f;

    #pragma unroll 1
    for (int kt = 0; kt <= qt; kt++) {
        __syncthreads();   // K/V/P buffers free
        #pragma unroll
        for (int qq = 0; qq < 8; qq++) {
            int d0 = (lqb + qq) * 4;
            const float* Kr = Kb + ((size_t)(kt * 64 + lrow)) * D_;
            float4 kv = *(const float4*)(Kr + d0);
            *(float4*)&Kf[lrow * AST_ + d0] = kv;
            const float* Vr = Vb + ((size_t)(kt * 64 + lrow)) * D_;
            float4 vv = *(const float4*)(Vr + d0);
            Vs[(d0 + 0) * AST_ + lrow] = f2tf32(vv.x);
            Vs[(d0 + 1) * AST_ + lrow] = f2tf32(vv.y);
            Vs[(d0 + 2) * AST_ + lrow] = f2tf32(vv.z);
            Vs[(d0 + 3) * AST_ + lrow] = f2tf32(vv.w);
        }
        __syncthreads();

        // ---- S = Q K^T (2xTF32: qh*kh + qh*kl) ----
        float sacc[8][4];
        #pragma unroll
        for (int nt = 0; nt < 8; nt++)
            #pragma unroll
            for (int c = 0; c < 4; c++) sacc[nt][c] = 0.f;

        #pragma unroll
        for (int ks = 0; ks < 8; ks++) {
            const int abase = (w * 16 + g) * AST_ + ks * 8 + tg;
            uint32_t af[4];
            af[0] = Qs[abase];
            af[1] = Qs[abase + 8 * AST_];
            af[2] = Qs[abase + 4];
            af[3] = Qs[abase + 8 * AST_ + 4];
            #pragma unroll
            for (int nt = 0; nt < 8; nt++) {
                const int bbase = (nt * 8 + g) * AST_ + ks * 8 + tg;
                float b0 = Kf[bbase], b1 = Kf[bbase + 4];
                uint32_t bh[2], bl[2];
                bh[0] = f2tf32(b0); bl[0] = f2tf32(b0 - __uint_as_float(bh[0]));
                bh[1] = f2tf32(b1); bl[1] = f2tf32(b1 - __uint_as_float(bh[1]));
                mma_tf32(sacc[nt], af, bh);
                mma_tf32(sacc[nt], af, bl);
            }
        }

        // ---- masking (diag tile only) ----
        if (kt == qt) {
            #pragma unroll
            for (int nt = 0; nt < 8; nt++)
                #pragma unroll
                for (int c = 0; c < 4; c++) {
                    int colL = nt * 8 + 2 * tg + (c & 1);
                    int rowL = w * 16 + g + 8 * (c >> 1);
                    if (colL > rowL) sacc[nt][c] = -INFINITY;
                }
        }

        // ---- online softmax (rows g, g+8; stats replicated over tg quad) ----
        float rm[2] = {-INFINITY, -INFINITY};
        #pragma unroll
        for (int nt = 0; nt < 8; nt++) {
            rm[0] = fmaxf(rm[0], fmaxf(sacc[nt][0], sacc[nt][1]));
            rm[1] = fmaxf(rm[1], fmaxf(sacc[nt][2], sacc[nt][3]));
        }
        #pragma unroll
        for (int r = 0; r < 2; r++) {
            rm[r] = fmaxf(rm[r], __shfl_xor_sync(0xffffffffu, rm[r], 1));
            rm[r] = fmaxf(rm[r], __shfl_xor_sync(0xffffffffu, rm[r], 2));
        }
        float alpha[2], rs[2];
        #pragma unroll
        for (int r = 0; r < 2; r++) {
            float mn = fmaxf(m[r], rm[r]);
            alpha[r] = __expf(m[r] - mn);
            m[r] = mn;
            rs[r] = 0.f;
        }
        #pragma unroll
        for (int nt = 0; nt < 8; nt++) {
            #pragma unroll
            for (int c = 0; c < 4; c++) {
                int r = c >> 1;
                float p = __expf(sacc[nt][c] - m[r]);
                sacc[nt][c] = p;
                rs[r] += p;
            }
        }
        #pragma unroll
        for (int r = 0; r < 2; r++) {
            rs[r] += __shfl_xor_sync(0xffffffffu, rs[r], 1);
            rs[r] += __shfl_xor_sync(0xffffffffu, rs[r], 2);
            l[r] = l[r] * alpha[r] + rs[r];
        }
        #pragma unroll
        for (int nt = 0; nt < 8; nt++) {
            o[nt][0] *= alpha[0]; o[nt][1] *= alpha[0];
            o[nt][2] *= alpha[1]; o[nt][3] *= alpha[1];
        }

        // ---- store P^T [k][q] (warp-private columns) ----
        #pragma unroll
        for (int nt = 0; nt < 8; nt++)
            #pragma unroll
            for (int c = 0; c < 4; c++) {
                int kpos = nt * 8 + 2 * tg + (c & 1);
                int qrow = w * 16 + g + 8 * (c >> 1);
                Ps[kpos * AST_ + qrow] = f2tf32(sacc[nt][c]);
            }
        __syncwarp();

        // ---- O += P V ----
        #pragma unroll
        for (int ks = 0; ks < 8; ks++) {
            const int pbase = (ks * 8 + tg) * AST_ + w * 16 + g;
            uint32_t pa[4];
            pa[0] = Ps[pbase];
            pa[1] = Ps[pbase + 8];
            pa[2] = Ps[pbase + 4 * AST_];
            pa[3] = Ps[pbase + 4 * AST_ + 8];
            #pragma unroll
            for (int nt = 0; nt < 8; nt++) {
                const int vbase = (nt * 8 + g) * AST_ + ks * 8 + tg;
                uint32_t vb[2];
                vb[0] = Vs[vbase];
                vb[1] = Vs[vbase + 4];
                mma_tf32(o[nt], pa, vb);
            }
        }
    }

    // ---- finalize & store ----
    float inv[2] = { 1.0f / l[0], 1.0f / l[1] };
    float* Ob = g_Att + ((size_t)b * S_ + qt * 64) * D_ + h * 64;
    #pragma unroll
    for (int nt = 0; nt < 8; nt++)
        #pragma unroll
        for (int r = 0; r < 2; r++) {
            int row = w * 16 + g + 8 * r;
            int col = nt * 8 + 2 * tg;
            float2 ov = { o[nt][2 * r] * inv[r], o[nt][2 * r + 1] * inv[r] };
            *(float2*)(Ob + (size_t)row * D_ + col) = ov;
        }
}

// ---------------------------------------------------------------------------
extern "C" void kernel_launch(void* const* d_in, const int* in_sizes, int n_in,
                              void* d_out, int out_size)
{
    (void)in_sizes; (void)n_in; (void)out_size;
    const float* q  = (const float*)d_in[0];
    const float* k  = (const float*)d_in[1];
    const float* v  = (const float*)d_in[2];
    const float* Wq = (const float*)d_in[4];
    const float* bq = (const float*)d_in[5];
    const float* Wk = (const float*)d_in[6];
    const float* bk = (const float*)d_in[7];
    const float* Wv = (const float*)d_in[8];
    const float* bv = (const float*)d_in[9];
    const float* Wo = (const float*)d_in[10];
    const float* bo = (const float*)d_in[11];
    float* out = (float*)d_out;

    const int gemm_smem = 4 * STAGE_WORDS_ * 4;      // 67584 B
    cudaFuncSetAttribute(qkv_gemm_mma, cudaFuncAttributeMaxDynamicSharedMemorySize, gemm_smem);
    cudaFuncSetAttribute(out_gemm_mma, cudaFuncAttributeMaxDynamicSharedMemorySize, gemm_smem);
    const int attn_smem = 4 * 64 * AST_ * 4;         // 69632 B
    cudaFuncSetAttribute(attn_kernel, cudaFuncAttributeMaxDynamicSharedMemorySize, attn_smem);

    dim3 gqkv(1024/128, M_/128, 3);
    qkv_gemm_mma<<<gqkv, 256, gemm_smem>>>(q, k, v, Wq, bq, Wk, bk, Wv, bv);

    attn_kernel<<<dim3(S_/64, H_, B_), 128, attn_smem>>>();

    out_gemm_mma<<<dim3(1024/128, M_/128), 256, gemm_smem>>>(Wo, bo, out);
}

// round 6
// speedup vs baseline: 2.6747x; 1.4434x over previous
#include <cuda_runtime.h>
#include <math.h>
#include <stdint.h>

#define B_ 2
#define S_ 2048
#define D_ 1024
#define H_ 16
#define M_ (B_*S_)

// Scratch (allocation-free rule: __device__ globals)
__device__ float g_Qp[(size_t)B_*S_*D_];
__device__ float g_Kp[(size_t)B_*S_*D_];
__device__ float g_Vp[(size_t)B_*S_*D_];
__device__ float g_Att[(size_t)B_*S_*D_];

__device__ __forceinline__ uint32_t f2tf32(float x) {
    uint32_t r;
    asm("cvt.rna.tf32.f32 %0, %1;" : "=r"(r) : "f"(x));
    return r;
}

__device__ __forceinline__ void mma_tf32(float* d, const uint32_t* a, const uint32_t* b) {
    asm volatile(
        "mma.sync.aligned.m16n8k8.row.col.f32.tf32.tf32.f32 "
        "{%0,%1,%2,%3}, {%4,%5,%6,%7}, {%8,%9}, {%0,%1,%2,%3};"
        : "+f"(d[0]), "+f"(d[1]), "+f"(d[2]), "+f"(d[3])
        : "r"(a[0]), "r"(a[1]), "r"(a[2]), "r"(a[3]), "r"(b[0]), "r"(b[1]));
}

__device__ __forceinline__ uint32_t smem_u32(const void* p) {
    uint32_t a;
    asm("{ .reg .u64 t; cvta.to.shared.u64 t, %1; cvt.u32.u64 %0, t; }"
        : "=r"(a) : "l"(p));
    return a;
}

__device__ __forceinline__ void cp_async16(uint32_t saddr, const void* g) {
    asm volatile("cp.async.cg.shared.global [%0], [%1], 16;"
                 :: "r"(saddr), "l"(g) : "memory");
}
#define CP_COMMIT()  asm volatile("cp.async.commit_group;" ::: "memory")
#define CP_WAIT(n_)  asm volatile("cp.async.wait_group %0;" :: "n"(n_) : "memory")

// ---------------------------------------------------------------------------
// tf32 mma.sync GEMM v2: C[M,N] = A[M,K] @ W[N,K]^T + bias  (K=1024, N=1024)
// CTA 128x128, BK=32, 256 threads (8 warps 2x4), warp tile 64x32.
// cp.async double-buffered raw-fp32 smem, row-major [r][k] stride 36
// (bank = 4g+tg: conflict-free fragment loads). tf32 cvt at fragment load.
// ---------------------------------------------------------------------------
#define GST_ 36
#define GSTAGE_ (128*GST_)

template<int DO_ROPE>
__device__ __forceinline__ void gemm_mma_body(const float* __restrict__ A,
                                              const float* __restrict__ W,
                                              const float* __restrict__ bias,
                                              float* __restrict__ C)
{
    extern __shared__ float gsm_[];
    float* Asf = gsm_;                    // [2][128][36]
    float* Bsf = gsm_ + 2 * GSTAGE_;      // [2][128][36]

    const int tid  = threadIdx.x;
    const int lane = tid & 31, w = tid >> 5;
    const int warpM = w & 1, warpN = w >> 1;
    const int g = lane >> 2, tg = lane & 3;
    const int m0 = blockIdx.y * 128, n0 = blockIdx.x * 128;

    const uint32_t sA_u = smem_u32(Asf);
    const uint32_t sB_u = smem_u32(Bsf);

    #define ISSUE_STAGE(s_, buf_) do {                                        \
        const int k0_ = (s_) * 32;                                            \
        _Pragma("unroll")                                                     \
        for (int t = 0; t < 4; t++) {                                         \
            int slot = tid + t * 256;                                         \
            int r = slot >> 3, qd = slot & 7;                                 \
            uint32_t so = (uint32_t)(((buf_) * GSTAGE_ + r * GST_ + qd * 4) * 4); \
            cp_async16(sA_u + so, A + (size_t)(m0 + r) * 1024 + k0_ + qd * 4);\
            cp_async16(sB_u + so, W + (size_t)(n0 + r) * 1024 + k0_ + qd * 4);\
        }                                                                     \
    } while (0)

    float acc[4][4][4];
    #pragma unroll
    for (int i = 0; i < 4; i++)
        #pragma unroll
        for (int j = 0; j < 4; j++)
            #pragma unroll
            for (int x = 0; x < 4; x++) acc[i][j][x] = 0.f;

    ISSUE_STAGE(0, 0);
    CP_COMMIT();

    #pragma unroll 1
    for (int s = 0; s < 32; s++) {
        if (s + 1 < 32) {
            ISSUE_STAGE(s + 1, (s + 1) & 1);
            CP_COMMIT();
            CP_WAIT(1);
        } else {
            CP_WAIT(0);
        }
        __syncthreads();

        const float* Ab = Asf + (s & 1) * GSTAGE_;
        const float* Bb = Bsf + (s & 1) * GSTAGE_;
        #pragma unroll
        for (int ks = 0; ks < 4; ks++) {
            const int kc = ks * 8 + tg;
            uint32_t af[4][4];
            #pragma unroll
            for (int mt = 0; mt < 4; mt++) {
                const float* p = Ab + (warpM * 64 + mt * 16 + g) * GST_ + kc;
                af[mt][0] = f2tf32(p[0]);
                af[mt][1] = f2tf32(p[8 * GST_]);
                af[mt][2] = f2tf32(p[4]);
                af[mt][3] = f2tf32(p[8 * GST_ + 4]);
            }
            uint32_t bf[4][2];
            #pragma unroll
            for (int nt = 0; nt < 4; nt++) {
                const float* p = Bb + (warpN * 8 + nt * 32 + g) * GST_ + kc;
                bf[nt][0] = f2tf32(p[0]);
                bf[nt][1] = f2tf32(p[4]);
            }
            #pragma unroll
            for (int mt = 0; mt < 4; mt++)
                #pragma unroll
                for (int nt = 0; nt < 4; nt++)
                    mma_tf32(acc[mt][nt], af[mt], bf[nt]);
        }
        __syncthreads();
    }
    #undef ISSUE_STAGE

    float bcol[4][2];
    #pragma unroll
    for (int nt = 0; nt < 4; nt++) {
        bcol[nt][0] = bias[n0 + warpN * 8 + nt * 32 + 2 * tg + 0];
        bcol[nt][1] = bias[n0 + warpN * 8 + nt * 32 + 2 * tg + 1];
    }
    #pragma unroll
    for (int mt = 0; mt < 4; mt++)
        #pragma unroll
        for (int nt = 0; nt < 4; nt++) {
            acc[mt][nt][0] += bcol[nt][0];
            acc[mt][nt][1] += bcol[nt][1];
            acc[mt][nt][2] += bcol[nt][0];
            acc[mt][nt][3] += bcol[nt][1];
        }

    if (DO_ROPE) {
        float sn[2][8], cs[2][8];
        #pragma unroll
        for (int jj = 0; jj < 2; jj++) {
            int jcol = warpN * 8 + 2 * tg + jj;
            float invf = (float)exp(-(double)jcol * 0.28782313662425574);
            #pragma unroll
            for (int mt = 0; mt < 4; mt++)
                #pragma unroll
                for (int half = 0; half < 2; half++) {
                    int row = m0 + warpM * 64 + mt * 16 + g + 8 * half;
                    float sp = (float)(row & (S_ - 1));
                    sincosf(sp * invf, &sn[jj][mt * 2 + half], &cs[jj][mt * 2 + half]);
                }
        }
        #pragma unroll
        for (int mt = 0; mt < 4; mt++)
            #pragma unroll
            for (int p = 0; p < 2; p++)
                #pragma unroll
                for (int idx = 0; idx < 4; idx++) {
                    int jj = idx & 1, half = idx >> 1;
                    float c = cs[jj][mt * 2 + half], s = sn[jj][mt * 2 + half];
                    float x1 = acc[mt][2 * p][idx], x2 = acc[mt][2 * p + 1][idx];
                    acc[mt][2 * p][idx]     = x1 * c - x2 * s;
                    acc[mt][2 * p + 1][idx] = x1 * s + x2 * c;
                }
    }

    #pragma unroll
    for (int mt = 0; mt < 4; mt++)
        #pragma unroll
        for (int nt = 0; nt < 4; nt++)
            #pragma unroll
            for (int half = 0; half < 2; half++) {
                int row = m0 + warpM * 64 + mt * 16 + g + 8 * half;
                int col = n0 + warpN * 8 + nt * 32 + 2 * tg;
                float2 ov = { acc[mt][nt][half * 2], acc[mt][nt][half * 2 + 1] };
                *(float2*)(C + (size_t)row * 1024 + col) = ov;
            }
}

__global__ __launch_bounds__(256, 2)
void qkv_gemm_mma(const float* __restrict__ q, const float* __restrict__ k,
                  const float* __restrict__ v,
                  const float* __restrict__ Wq, const float* __restrict__ bq,
                  const float* __restrict__ Wk, const float* __restrict__ bk,
                  const float* __restrict__ Wv, const float* __restrict__ bv)
{
    if (blockIdx.z == 0)      gemm_mma_body<1>(q, Wq, bq, g_Qp);
    else if (blockIdx.z == 1) gemm_mma_body<1>(k, Wk, bk, g_Kp);
    else                      gemm_mma_body<0>(v, Wv, bv, g_Vp);
}

__global__ __launch_bounds__(256, 2)
void out_gemm_mma(const float* __restrict__ Wo, const float* __restrict__ bo,
                  float* __restrict__ out)
{
    gemm_mma_body<0>(g_Att, Wo, bo, out);
}

// ---------------------------------------------------------------------------
// Causal flash attention v3: 128 threads, 64x64 tiles, 2xTF32 scores,
// cp.async double-buffered K/V prefetch (raw fp32 [k][d] tiles).
//  - Qs: tf32 [q][d]  (Q pre-scaled 1/8)
//  - Kraw[2]: fp32 [k][d]  (hi/lo split in registers at fragment load)
//  - Vraw[2]: fp32 [k][d]  (cvt tf32 at fragment load; <=2-way conflicts)
//  - Ps: tf32 [k][q]
// smem = 6*64*68*4 = 104448 B -> 2 CTAs/SM, gmem latency prefetched.
// ---------------------------------------------------------------------------
#define AST_ 68
__global__ __launch_bounds__(128) void attn_kernel()
{
    extern __shared__ uint32_t asm_[];
    uint32_t* Qs   = asm_;
    float*    Kraw = (float*)(asm_ + 1 * 64 * AST_);   // [2][64][68]
    float*    Vraw = (float*)(asm_ + 3 * 64 * AST_);   // [2][64][68]
    uint32_t* Ps   = asm_ + 5 * 64 * AST_;

    const int tid = threadIdx.x;
    const int lane = tid & 31, w = tid >> 5;
    const int g = lane >> 2, tg = lane & 3;
    const int qt = (int)(gridDim.x - 1) - (int)blockIdx.x;   // heavy first
    const int h = blockIdx.y, b = blockIdx.z;

    const float* Qb = g_Qp + ((size_t)b * S_ + qt * 64) * D_ + h * 64;
    const float* Kb = g_Kp + (size_t)b * S_ * D_ + h * 64;
    const float* Vb = g_Vp + (size_t)b * S_ * D_ + h * 64;

    const uint32_t kraw_u = smem_u32(Kraw);
    const uint32_t vraw_u = smem_u32(Vraw);

    #define ISSUE_KV(kt_, buf_) do {                                          \
        _Pragma("unroll")                                                     \
        for (int t = 0; t < 8; t++) {                                         \
            int slot = tid + t * 128;                                         \
            int r = slot >> 4, qd = slot & 15;                                \
            uint32_t so = (uint32_t)((((buf_) * 64 + r) * AST_ + qd * 4) * 4);\
            const size_t go = (size_t)((kt_) * 64 + r) * D_ + qd * 4;         \
            cp_async16(kraw_u + so, Kb + go);                                 \
            cp_async16(vraw_u + so, Vb + go);                                 \
        }                                                                     \
    } while (0)

    ISSUE_KV(0, 0);
    CP_COMMIT();

    const int lrow = tid >> 1;
    const int lqb  = (tid & 1) * 8;

    // ---- load Q once: scale 1/8, tf32, [q][d] ----
    #pragma unroll
    for (int qq = 0; qq < 8; qq++) {
        int d0 = (lqb + qq) * 4;
        float4 qv = *(const float4*)(Qb + (size_t)lrow * D_ + d0);
        uint4 tq = { f2tf32(qv.x * 0.125f), f2tf32(qv.y * 0.125f),
                     f2tf32(qv.z * 0.125f), f2tf32(qv.w * 0.125f) };
        *(uint4*)&Qs[lrow * AST_ + d0] = tq;
    }

    float m[2], l[2], o[8][4];
    m[0] = m[1] = -INFINITY; l[0] = l[1] = 0.f;
    #pragma unroll
    for (int nt = 0; nt < 8; nt++)
        #pragma unroll
        for (int c = 0; c < 4; c++) o[nt][c] = 0.f;

    #pragma unroll 1
    for (int kt = 0; kt <= qt; kt++) {
        if (kt + 1 <= qt) {
            ISSUE_KV(kt + 1, (kt + 1) & 1);
            CP_COMMIT();
            CP_WAIT(1);
        } else {
            CP_WAIT(0);
        }
        __syncthreads();

        const float* Kt = Kraw + (size_t)(kt & 1) * 64 * AST_;
        const float* Vt = Vraw + (size_t)(kt & 1) * 64 * AST_;

        // ---- S = Q K^T (2xTF32: qh*kh + qh*kl) ----
        float sacc[8][4];
        #pragma unroll
        for (int nt = 0; nt < 8; nt++)
            #pragma unroll
            for (int c = 0; c < 4; c++) sacc[nt][c] = 0.f;

        #pragma unroll
        for (int ks = 0; ks < 8; ks++) {
            const int abase = (w * 16 + g) * AST_ + ks * 8 + tg;
            uint32_t af[4];
            af[0] = Qs[abase];
            af[1] = Qs[abase + 8 * AST_];
            af[2] = Qs[abase + 4];
            af[3] = Qs[abase + 8 * AST_ + 4];
            #pragma unroll
            for (int nt = 0; nt < 8; nt++) {
                const int bbase = (nt * 8 + g) * AST_ + ks * 8 + tg;
                float b0 = Kt[bbase], b1 = Kt[bbase + 4];
                uint32_t bh[2], bl[2];
                bh[0] = f2tf32(b0); bl[0] = f2tf32(b0 - __uint_as_float(bh[0]));
                bh[1] = f2tf32(b1); bl[1] = f2tf32(b1 - __uint_as_float(bh[1]));
                mma_tf32(sacc[nt], af, bh);
                mma_tf32(sacc[nt], af, bl);
            }
        }

        // ---- masking (diag tile only) ----
        if (kt == qt) {
            #pragma unroll
            for (int nt = 0; nt < 8; nt++)
                #pragma unroll
                for (int c = 0; c < 4; c++) {
                    int colL = nt * 8 + 2 * tg + (c & 1);
                    int rowL = w * 16 + g + 8 * (c >> 1);
                    if (colL > rowL) sacc[nt][c] = -INFINITY;
                }
        }

        // ---- online softmax (rows g, g+8; stats replicated over tg quad) ----
        float rm[2] = {-INFINITY, -INFINITY};
        #pragma unroll
        for (int nt = 0; nt < 8; nt++) {
            rm[0] = fmaxf(rm[0], fmaxf(sacc[nt][0], sacc[nt][1]));
            rm[1] = fmaxf(rm[1], fmaxf(sacc[nt][2], sacc[nt][3]));
        }
        #pragma unroll
        for (int r = 0; r < 2; r++) {
            rm[r] = fmaxf(rm[r], __shfl_xor_sync(0xffffffffu, rm[r], 1));
            rm[r] = fmaxf(rm[r], __shfl_xor_sync(0xffffffffu, rm[r], 2));
        }
        float alpha[2], rs[2];
        #pragma unroll
        for (int r = 0; r < 2; r++) {
            float mn = fmaxf(m[r], rm[r]);
            alpha[r] = __expf(m[r] - mn);
            m[r] = mn;
            rs[r] = 0.f;
        }
        #pragma unroll
        for (int nt = 0; nt < 8; nt++) {
            #pragma unroll
            for (int c = 0; c < 4; c++) {
                int r = c >> 1;
                float p = __expf(sacc[nt][c] - m[r]);
                sacc[nt][c] = p;
                rs[r] += p;
            }
        }
        #pragma unroll
        for (int r = 0; r < 2; r++) {
            rs[r] += __shfl_xor_sync(0xffffffffu, rs[r], 1);
            rs[r] += __shfl_xor_sync(0xffffffffu, rs[r], 2);
            l[r] = l[r] * alpha[r] + rs[r];
        }
        #pragma unroll
        for (int nt = 0; nt < 8; nt++) {
            o[nt][0] *= alpha[0]; o[nt][1] *= alpha[0];
            o[nt][2] *= alpha[1]; o[nt][3] *= alpha[1];
        }

        // ---- store P^T [k][q] (warp-private columns) ----
        #pragma unroll
        for (int nt = 0; nt < 8; nt++)
            #pragma unroll
            for (int c = 0; c < 4; c++) {
                int kpos = nt * 8 + 2 * tg + (c & 1);
                int qrow = w * 16 + g + 8 * (c >> 1);
                Ps[kpos * AST_ + qrow] = f2tf32(sacc[nt][c]);
            }
        __syncwarp();

        // ---- O += P V ----
        #pragma unroll
        for (int ks = 0; ks < 8; ks++) {
            const int pbase = (ks * 8 + tg) * AST_ + w * 16 + g;
            uint32_t pa[4];
            pa[0] = Ps[pbase];
            pa[1] = Ps[pbase + 8];
            pa[2] = Ps[pbase + 4 * AST_];
            pa[3] = Ps[pbase + 4 * AST_ + 8];
            #pragma unroll
            for (int nt = 0; nt < 8; nt++) {
                const int vbase = (ks * 8 + tg) * AST_ + nt * 8 + g;
                uint32_t vb[2];
                vb[0] = f2tf32(Vt[vbase]);
                vb[1] = f2tf32(Vt[vbase + 4 * AST_]);
                mma_tf32(o[nt], pa, vb);
            }
        }
        __syncthreads();   // all warps done with Kt/Vt before next issue overwrites
    }
    #undef ISSUE_KV

    // ---- finalize & store ----
    float inv[2] = { 1.0f / l[0], 1.0f / l[1] };
    float* Ob = g_Att + ((size_t)b * S_ + qt * 64) * D_ + h * 64;
    #pragma unroll
    for (int nt = 0; nt < 8; nt++)
        #pragma unroll
        for (int r = 0; r < 2; r++) {
            int row = w * 16 + g + 8 * r;
            int col = nt * 8 + 2 * tg;
            float2 ov = { o[nt][2 * r] * inv[r], o[nt][2 * r + 1] * inv[r] };
            *(float2*)(Ob + (size_t)row * D_ + col) = ov;
        }
}

// ---------------------------------------------------------------------------
extern "C" void kernel_launch(void* const* d_in, const int* in_sizes, int n_in,
                              void* d_out, int out_size)
{
    (void)in_sizes; (void)n_in; (void)out_size;
    const float* q  = (const float*)d_in[0];
    const float* k  = (const float*)d_in[1];
    const float* v  = (const float*)d_in[2];
    const float* Wq = (const float*)d_in[4];
    const float* bq = (const float*)d_in[5];
    const float* Wk = (const float*)d_in[6];
    const float* bk = (const float*)d_in[7];
    const float* Wv = (const float*)d_in[8];
    const float* bv = (const float*)d_in[9];
    const float* Wo = (const float*)d_in[10];
    const float* bo = (const float*)d_in[11];
    float* out = (float*)d_out;

    const int gemm_smem = 4 * GSTAGE_ * 4;           // 73728 B
    cudaFuncSetAttribute(qkv_gemm_mma, cudaFuncAttributeMaxDynamicSharedMemorySize, gemm_smem);
    cudaFuncSetAttribute(out_gemm_mma, cudaFuncAttributeMaxDynamicSharedMemorySize, gemm_smem);
    const int attn_smem = 6 * 64 * AST_ * 4;         // 104448 B
    cudaFuncSetAttribute(attn_kernel, cudaFuncAttributeMaxDynamicSharedMemorySize, attn_smem);

    dim3 gqkv(1024/128, M_/128, 3);
    qkv_gemm_mma<<<gqkv, 256, gemm_smem>>>(q, k, v, Wq, bq, Wk, bk, Wv, bv);

    attn_kernel<<<dim3(S_/64, H_, B_), 128, attn_smem>>>();

    out_gemm_mma<<<dim3(1024/128, M_/128), 256, gemm_smem>>>(Wo, bo, out);
}

// round 7
// speedup vs baseline: 2.7381x; 1.0237x over previous
#include <cuda_runtime.h>
#include <math.h>
#include <stdint.h>

#define B_ 2
#define S_ 2048
#define D_ 1024
#define H_ 16
#define M_ (B_*S_)

// Scratch (allocation-free rule: __device__ globals)
__device__ float g_Qp[(size_t)B_*S_*D_];
__device__ float g_Kp[(size_t)B_*S_*D_];
__device__ float g_Vp[(size_t)B_*S_*D_];
__device__ float g_Att[(size_t)B_*S_*D_];

__device__ __forceinline__ uint32_t f2tf32(float x) {
    uint32_t r;
    asm("cvt.rna.tf32.f32 %0, %1;" : "=r"(r) : "f"(x));
    return r;
}

__device__ __forceinline__ void mma_tf32(float* d, const uint32_t* a, const uint32_t* b) {
    asm volatile(
        "mma.sync.aligned.m16n8k8.row.col.f32.tf32.tf32.f32 "
        "{%0,%1,%2,%3}, {%4,%5,%6,%7}, {%8,%9}, {%0,%1,%2,%3};"
        : "+f"(d[0]), "+f"(d[1]), "+f"(d[2]), "+f"(d[3])
        : "r"(a[0]), "r"(a[1]), "r"(a[2]), "r"(a[3]), "r"(b[0]), "r"(b[1]));
}

__device__ __forceinline__ uint32_t smem_u32(const void* p) {
    uint32_t a;
    asm("{ .reg .u64 t; cvta.to.shared.u64 t, %1; cvt.u32.u64 %0, t; }"
        : "=r"(a) : "l"(p));
    return a;
}

__device__ __forceinline__ void cp_async16(uint32_t saddr, const void* g) {
    asm volatile("cp.async.cg.shared.global [%0], [%1], 16;"
                 :: "r"(saddr), "l"(g) : "memory");
}
#define CP_COMMIT()  asm volatile("cp.async.commit_group;" ::: "memory")
#define CP_WAIT(n_)  asm volatile("cp.async.wait_group %0;" :: "n"(n_) : "memory")

// ---------------------------------------------------------------------------
// tf32 mma.sync GEMM v3: 3-stage cp.async pipeline, one sync per stage.
// CTA 128x128, BK=32, 256 threads (8 warps 2x4), warp tile 64x32.
// raw-fp32 smem [r][k] stride 36 (conflict-free); tf32 cvt at fragment load.
// ---------------------------------------------------------------------------
#define GST_ 36
#define GSTAGE_ (128*GST_)

template<int DO_ROPE>
__device__ __forceinline__ void gemm_mma_body(const float* __restrict__ A,
                                              const float* __restrict__ W,
                                              const float* __restrict__ bias,
                                              float* __restrict__ C)
{
    extern __shared__ float gsm_[];
    float* Asf = gsm_;                    // [3][128][36]
    float* Bsf = gsm_ + 3 * GSTAGE_;      // [3][128][36]

    const int tid  = threadIdx.x;
    const int lane = tid & 31, w = tid >> 5;
    const int warpM = w & 1, warpN = w >> 1;
    const int g = lane >> 2, tg = lane & 3;
    const int m0 = blockIdx.y * 128, n0 = blockIdx.x * 128;

    const uint32_t sA_u = smem_u32(Asf);
    const uint32_t sB_u = smem_u32(Bsf);

    #define ISSUE_STAGE(s_, buf_) do {                                        \
        const int k0_ = (s_) * 32;                                            \
        _Pragma("unroll")                                                     \
        for (int t = 0; t < 4; t++) {                                         \
            int slot = tid + t * 256;                                         \
            int r = slot >> 3, qd = slot & 7;                                 \
            uint32_t so = (uint32_t)(((buf_) * GSTAGE_ + r * GST_ + qd * 4) * 4); \
            cp_async16(sA_u + so, A + (size_t)(m0 + r) * 1024 + k0_ + qd * 4);\
            cp_async16(sB_u + so, W + (size_t)(n0 + r) * 1024 + k0_ + qd * 4);\
        }                                                                     \
    } while (0)

    float acc[4][4][4];
    #pragma unroll
    for (int i = 0; i < 4; i++)
        #pragma unroll
        for (int j = 0; j < 4; j++)
            #pragma unroll
            for (int x = 0; x < 4; x++) acc[i][j][x] = 0.f;

    ISSUE_STAGE(0, 0); CP_COMMIT();
    ISSUE_STAGE(1, 1); CP_COMMIT();

    int cur = 0, nxt = 2;
    #pragma unroll 1
    for (int s = 0; s < 32; s++) {
        if (s < 31) { CP_WAIT(1); } else { CP_WAIT(0); }
        __syncthreads();   // stage s visible; all threads done with stage s-1
        if (s + 2 < 32) {
            ISSUE_STAGE(s + 2, nxt);
            CP_COMMIT();
            if (++nxt == 3) nxt = 0;
        }

        const float* Ab = Asf + cur * GSTAGE_;
        const float* Bb = Bsf + cur * GSTAGE_;
        if (++cur == 3) cur = 0;

        #pragma unroll
        for (int ks = 0; ks < 4; ks++) {
            const int kc = ks * 8 + tg;
            uint32_t af[4][4];
            #pragma unroll
            for (int mt = 0; mt < 4; mt++) {
                const float* p = Ab + (warpM * 64 + mt * 16 + g) * GST_ + kc;
                af[mt][0] = f2tf32(p[0]);
                af[mt][1] = f2tf32(p[8 * GST_]);
                af[mt][2] = f2tf32(p[4]);
                af[mt][3] = f2tf32(p[8 * GST_ + 4]);
            }
            uint32_t bf[4][2];
            #pragma unroll
            for (int nt = 0; nt < 4; nt++) {
                const float* p = Bb + (warpN * 8 + nt * 32 + g) * GST_ + kc;
                bf[nt][0] = f2tf32(p[0]);
                bf[nt][1] = f2tf32(p[4]);
            }
            #pragma unroll
            for (int mt = 0; mt < 4; mt++)
                #pragma unroll
                for (int nt = 0; nt < 4; nt++)
                    mma_tf32(acc[mt][nt], af[mt], bf[nt]);
        }
    }
    #undef ISSUE_STAGE

    float bcol[4][2];
    #pragma unroll
    for (int nt = 0; nt < 4; nt++) {
        bcol[nt][0] = bias[n0 + warpN * 8 + nt * 32 + 2 * tg + 0];
        bcol[nt][1] = bias[n0 + warpN * 8 + nt * 32 + 2 * tg + 1];
    }
    #pragma unroll
    for (int mt = 0; mt < 4; mt++)
        #pragma unroll
        for (int nt = 0; nt < 4; nt++) {
            acc[mt][nt][0] += bcol[nt][0];
            acc[mt][nt][1] += bcol[nt][1];
            acc[mt][nt][2] += bcol[nt][0];
            acc[mt][nt][3] += bcol[nt][1];
        }

    if (DO_ROPE) {
        float sn[2][8], cs[2][8];
        #pragma unroll
        for (int jj = 0; jj < 2; jj++) {
            int jcol = warpN * 8 + 2 * tg + jj;
            float invf = (float)exp(-(double)jcol * 0.28782313662425574);
            #pragma unroll
            for (int mt = 0; mt < 4; mt++)
                #pragma unroll
                for (int half = 0; half < 2; half++) {
                    int row = m0 + warpM * 64 + mt * 16 + g + 8 * half;
                    float sp = (float)(row & (S_ - 1));
                    sincosf(sp * invf, &sn[jj][mt * 2 + half], &cs[jj][mt * 2 + half]);
                }
        }
        #pragma unroll
        for (int mt = 0; mt < 4; mt++)
            #pragma unroll
            for (int p = 0; p < 2; p++)
                #pragma unroll
                for (int idx = 0; idx < 4; idx++) {
                    int jj = idx & 1, half = idx >> 1;
                    float c = cs[jj][mt * 2 + half], s = sn[jj][mt * 2 + half];
                    float x1 = acc[mt][2 * p][idx], x2 = acc[mt][2 * p + 1][idx];
                    acc[mt][2 * p][idx]     = x1 * c - x2 * s;
                    acc[mt][2 * p + 1][idx] = x1 * s + x2 * c;
                }
    }

    #pragma unroll
    for (int mt = 0; mt < 4; mt++)
        #pragma unroll
        for (int nt = 0; nt < 4; nt++)
            #pragma unroll
            for (int half = 0; half < 2; half++) {
                int row = m0 + warpM * 64 + mt * 16 + g + 8 * half;
                int col = n0 + warpN * 8 + nt * 32 + 2 * tg;
                float2 ov = { acc[mt][nt][half * 2], acc[mt][nt][half * 2 + 1] };
                *(float2*)(C + (size_t)row * 1024 + col) = ov;
            }
}

__global__ __launch_bounds__(256, 2)
void qkv_gemm_mma(const float* __restrict__ q, const float* __restrict__ k,
                  const float* __restrict__ v,
                  const float* __restrict__ Wq, const float* __restrict__ bq,
                  const float* __restrict__ Wk, const float* __restrict__ bk,
                  const float* __restrict__ Wv, const float* __restrict__ bv)
{
    if (blockIdx.z == 0)      gemm_mma_body<1>(q, Wq, bq, g_Qp);
    else if (blockIdx.z == 1) gemm_mma_body<1>(k, Wk, bk, g_Kp);
    else                      gemm_mma_body<0>(v, Wv, bv, g_Vp);
}

__global__ __launch_bounds__(256, 2)
void out_gemm_mma(const float* __restrict__ Wo, const float* __restrict__ bo,
                  float* __restrict__ out)
{
    gemm_mma_body<0>(g_Att, Wo, bo, out);
}

// ---------------------------------------------------------------------------
// Causal flash attention v4: 128 threads, 64x64 tiles, 2xTF32 scores.
//  - Q a-fragments in REGISTERS (loaded+cvt'd once; kt-invariant)
//  - Kraw[2]: fp32 [k][d], cp.async double-buffered prefetch
//  - Vraw:    fp32 [k][d], cp.async single buffer, issued at kt-top,
//             awaited only after softmax (hidden behind S-phase)
//  - Ps: tf32 [k][q]
// smem = 4*64*68*4 = 69632 B -> 3 CTAs/SM (12 warps) WITH prefetch.
// ---------------------------------------------------------------------------
#define AST_ 68
__global__ __launch_bounds__(128, 3) void attn_kernel()
{
    extern __shared__ float afm_[];
    float*    Kraw = afm_;                          // [2][64][68]
    float*    Vraw = afm_ + 2 * 64 * AST_;          // [64][68]
    uint32_t* Ps   = (uint32_t*)(afm_ + 3 * 64 * AST_);

    const int tid = threadIdx.x;
    const int lane = tid & 31, w = tid >> 5;
    const int g = lane >> 2, tg = lane & 3;
    const int qt = (int)(gridDim.x - 1) - (int)blockIdx.x;   // heavy first
    const int h = blockIdx.y, b = blockIdx.z;

    const float* Qb = g_Qp + ((size_t)b * S_ + qt * 64) * D_ + h * 64;
    const float* Kb = g_Kp + (size_t)b * S_ * D_ + h * 64;
    const float* Vb = g_Vp + (size_t)b * S_ * D_ + h * 64;

    const uint32_t kraw_u = smem_u32(Kraw);
    const uint32_t vraw_u = smem_u32(Vraw);

    #define ISSUE_K(kt_, buf_) do {                                           \
        _Pragma("unroll")                                                     \
        for (int t = 0; t < 8; t++) {                                         \
            int slot = tid + t * 128;                                         \
            int r = slot >> 4, qd = slot & 15;                                \
            uint32_t so = (uint32_t)((((buf_) * 64 + r) * AST_ + qd * 4) * 4);\
            cp_async16(kraw_u + so, Kb + (size_t)((kt_) * 64 + r) * D_ + qd * 4); \
        }                                                                     \
    } while (0)
    #define ISSUE_V(kt_) do {                                                 \
        _Pragma("unroll")                                                     \
        for (int t = 0; t < 8; t++) {                                         \
            int slot = tid + t * 128;                                         \
            int r = slot >> 4, qd = slot & 15;                                \
            uint32_t so = (uint32_t)((r * AST_ + qd * 4) * 4);                \
            cp_async16(vraw_u + so, Vb + (size_t)((kt_) * 64 + r) * D_ + qd * 4); \
        }                                                                     \
    } while (0)

    ISSUE_K(0, 0); CP_COMMIT();

    // ---- Q a-fragments into registers (scaled 1/8, tf32, kt-invariant) ----
    uint32_t qf[8][4];
    {
        const float* q0 = Qb + (size_t)(w * 16 + g) * D_;
        const float* q1 = Qb + (size_t)(w * 16 + g + 8) * D_;
        #pragma unroll
        for (int ks = 0; ks < 8; ks++) {
            int c = ks * 8 + tg;
            qf[ks][0] = f2tf32(q0[c]     * 0.125f);
            qf[ks][1] = f2tf32(q1[c]     * 0.125f);
            qf[ks][2] = f2tf32(q0[c + 4] * 0.125f);
            qf[ks][3] = f2tf32(q1[c + 4] * 0.125f);
        }
    }

    float m[2], l[2], o[8][4];
    m[0] = m[1] = -INFINITY; l[0] = l[1] = 0.f;
    #pragma unroll
    for (int nt = 0; nt < 8; nt++)
        #pragma unroll
        for (int c = 0; c < 4; c++) o[nt][c] = 0.f;

    #pragma unroll 1
    for (int kt = 0; kt <= qt; kt++) {
        // prior end-of-loop sync guarantees Vraw/Ps/other-K-buf free
        ISSUE_V(kt); CP_COMMIT();
        if (kt + 1 <= qt) {
            ISSUE_K(kt + 1, (kt + 1) & 1); CP_COMMIT();
            CP_WAIT(2);               // K(kt) arrived; V(kt), K(kt+1) pending
        } else {
            CP_WAIT(1);               // K(kt) arrived; V(kt) pending
        }
        __syncthreads();

        const float* Kt = Kraw + (kt & 1) * 64 * AST_;

        // ---- S = Q K^T (2xTF32: qh*kh + qh*kl) ----
        float sacc[8][4];
        #pragma unroll
        for (int nt = 0; nt < 8; nt++)
            #pragma unroll
            for (int c = 0; c < 4; c++) sacc[nt][c] = 0.f;

        #pragma unroll
        for (int ks = 0; ks < 8; ks++) {
            #pragma unroll
            for (int nt = 0; nt < 8; nt++) {
                const int bbase = (nt * 8 + g) * AST_ + ks * 8 + tg;
                float b0 = Kt[bbase], b1 = Kt[bbase + 4];
                uint32_t bh[2], bl[2];
                bh[0] = f2tf32(b0); bl[0] = f2tf32(b0 - __uint_as_float(bh[0]));
                bh[1] = f2tf32(b1); bl[1] = f2tf32(b1 - __uint_as_float(bh[1]));
                mma_tf32(sacc[nt], qf[ks], bh);
                mma_tf32(sacc[nt], qf[ks], bl);
            }
        }

        // ---- masking (diag tile only) ----
        if (kt == qt) {
            #pragma unroll
            for (int nt = 0; nt < 8; nt++)
                #pragma unroll
                for (int c = 0; c < 4; c++) {
                    int colL = nt * 8 + 2 * tg + (c & 1);
                    int rowL = w * 16 + g + 8 * (c >> 1);
                    if (colL > rowL) sacc[nt][c] = -INFINITY;
                }
        }

        // ---- online softmax (rows g, g+8; stats replicated over tg quad) ----
        float rm[2] = {-INFINITY, -INFINITY};
        #pragma unroll
        for (int nt = 0; nt < 8; nt++) {
            rm[0] = fmaxf(rm[0], fmaxf(sacc[nt][0], sacc[nt][1]));
            rm[1] = fmaxf(rm[1], fmaxf(sacc[nt][2], sacc[nt][3]));
        }
        #pragma unroll
        for (int r = 0; r < 2; r++) {
            rm[r] = fmaxf(rm[r], __shfl_xor_sync(0xffffffffu, rm[r], 1));
            rm[r] = fmaxf(rm[r], __shfl_xor_sync(0xffffffffu, rm[r], 2));
        }
        float alpha[2], rs[2];
        #pragma unroll
        for (int r = 0; r < 2; r++) {
            float mn = fmaxf(m[r], rm[r]);
            alpha[r] = __expf(m[r] - mn);
            m[r] = mn;
            rs[r] = 0.f;
        }
        #pragma unroll
        for (int nt = 0; nt < 8; nt++) {
            #pragma unroll
            for (int c = 0; c < 4; c++) {
                int r = c >> 1;
                float p = __expf(sacc[nt][c] - m[r]);
                sacc[nt][c] = p;
                rs[r] += p;
            }
        }
        #pragma unroll
        for (int r = 0; r < 2; r++) {
            rs[r] += __shfl_xor_sync(0xffffffffu, rs[r], 1);
            rs[r] += __shfl_xor_sync(0xffffffffu, rs[r], 2);
            l[r] = l[r] * alpha[r] + rs[r];
        }
        #pragma unroll
        for (int nt = 0; nt < 8; nt++) {
            o[nt][0] *= alpha[0]; o[nt][1] *= alpha[0];
            o[nt][2] *= alpha[1]; o[nt][3] *= alpha[1];
        }

        // ---- store P^T [k][q] (warp-private columns) ----
        #pragma unroll
        for (int nt = 0; nt < 8; nt++)
            #pragma unroll
            for (int c = 0; c < 4; c++) {
                int kpos = nt * 8 + 2 * tg + (c & 1);
                int qrow = w * 16 + g + 8 * (c >> 1);
                Ps[kpos * AST_ + qrow] = f2tf32(sacc[nt][c]);
            }

        // ---- V must be resident now (was hidden behind S + softmax) ----
        if (kt + 1 <= qt) { CP_WAIT(1); } else { CP_WAIT(0); }
        __syncthreads();   // V + Ps visible to all warps

        // ---- O += P V ----
        #pragma unroll
        for (int ks = 0; ks < 8; ks++) {
            const int pbase = (ks * 8 + tg) * AST_ + w * 16 + g;
            uint32_t pa[4];
            pa[0] = Ps[pbase];
            pa[1] = Ps[pbase + 8];
            pa[2] = Ps[pbase + 4 * AST_];
            pa[3] = Ps[pbase + 4 * AST_ + 8];
            #pragma unroll
            for (int nt = 0; nt < 8; nt++) {
                const int vbase = (ks * 8 + tg) * AST_ + nt * 8 + g;
                uint32_t vb[2];
                vb[0] = f2tf32(Vraw[vbase]);
                vb[1] = f2tf32(Vraw[vbase + 4 * AST_]);
                mma_tf32(o[nt], pa, vb);
            }
        }
        __syncthreads();   // all warps done with V/K/Ps before next kt's issues
    }
    #undef ISSUE_K
    #undef ISSUE_V

    // ---- finalize & store ----
    float inv[2] = { 1.0f / l[0], 1.0f / l[1] };
    float* Ob = g_Att + ((size_t)b * S_ + qt * 64) * D_ + h * 64;
    #pragma unroll
    for (int nt = 0; nt < 8; nt++)
        #pragma unroll
        for (int r = 0; r < 2; r++) {
            int row = w * 16 + g + 8 * r;
            int col = nt * 8 + 2 * tg;
            float2 ov = { o[nt][2 * r] * inv[r], o[nt][2 * r + 1] * inv[r] };
            *(float2*)(Ob + (size_t)row * D_ + col) = ov;
        }
}

// ---------------------------------------------------------------------------
extern "C" void kernel_launch(void* const* d_in, const int* in_sizes, int n_in,
                              void* d_out, int out_size)
{
    (void)in_sizes; (void)n_in; (void)out_size;
    const float* q  = (const float*)d_in[0];
    const float* k  = (const float*)d_in[1];
    const float* v  = (const float*)d_in[2];
    const float* Wq = (const float*)d_in[4];
    const float* bq = (const float*)d_in[5];
    const float* Wk = (const float*)d_in[6];
    const float* bk = (const float*)d_in[7];
    const float* Wv = (const float*)d_in[8];
    const float* bv = (const float*)d_in[9];
    const float* Wo = (const float*)d_in[10];
    const float* bo = (const float*)d_in[11];
    float* out = (float*)d_out;

    const int gemm_smem = 6 * GSTAGE_ * 4;           // 110592 B (3 stages)
    cudaFuncSetAttribute(qkv_gemm_mma, cudaFuncAttributeMaxDynamicSharedMemorySize, gemm_smem);
    cudaFuncSetAttribute(out_gemm_mma, cudaFuncAttributeMaxDynamicSharedMemorySize, gemm_smem);
    const int attn_smem = 4 * 64 * AST_ * 4;         // 69632 B -> 3 CTA/SM
    cudaFuncSetAttribute(attn_kernel, cudaFuncAttributeMaxDynamicSharedMemorySize, attn_smem);

    dim3 gqkv(1024/128, M_/128, 3);
    qkv_gemm_mma<<<gqkv, 256, gemm_smem>>>(q, k, v, Wq, bq, Wk, bk, Wv, bv);

    attn_kernel<<<dim3(S_/64, H_, B_), 128, attn_smem>>>();

    out_gemm_mma<<<dim3(1024/128, M_/128), 256, gemm_smem>>>(Wo, bo, out);
}